// round 4
// baseline (speedup 1.0000x reference)
#include <cuda_runtime.h>

// Problem constants
#define S_LEN 2048
#define BATCH 2
#define HEADS 16
#define HD    64
#define DM    1024
#define BH    (BATCH*HEADS)     // 32
#define MROWS (BATCH*S_LEN)     // 4096
#define SCALE 0.125f            // 1/sqrt(64)

// ---------------------------------------------------------------------------
// Scratch (no allocation allowed -> __device__ globals)
// ---------------------------------------------------------------------------
__device__ float g_Qt [(size_t)BH * HD * S_LEN];   // [bh][d][s]  (transposed for attention)
__device__ float g_Kt [(size_t)BH * HD * S_LEN];   // [bh][d][s]
__device__ float g_V  [(size_t)BH * S_LEN * HD];   // [bh][s][d]
__device__ float g_ctx[(size_t)MROWS * DM];        // attention context, [b*s][h*64+d]
__device__ float g_inv[BH * S_LEN];                // 1/rowsum for softmax normalize pass

// ---------------------------------------------------------------------------
// Shared 128x128x(K=1024) NT GEMM mainloop: C[m][n] = sum_k A[m][k]*B[n][k]
// 256 threads, 8x8 per-thread tile, BK=16, float4 smem fragments.
// ---------------------------------------------------------------------------
__device__ __forceinline__ void gemm_mainloop(
    const float* __restrict__ A, const float* __restrict__ B,
    int m0, int n0, float (&acc)[8][8],
    float (*As)[128], float (*Bs)[128])
{
    const int tid = threadIdx.x;
    const int tx  = tid & 15;
    const int ty  = tid >> 4;
    const int lr  = tid >> 2;          // 0..63
    const int lc  = (tid & 3) << 2;    // 0,4,8,12

    const float* Ap = A + (size_t)(m0 + lr) * DM + lc;
    const float* Bp = B + (size_t)(n0 + lr) * DM + lc;

    #pragma unroll 1
    for (int kt = 0; kt < DM; kt += 16) {
        float4 a0 = *(const float4*)(Ap + kt);
        float4 a1 = *(const float4*)(Ap + (size_t)64 * DM + kt);
        float4 b0 = *(const float4*)(Bp + kt);
        float4 b1 = *(const float4*)(Bp + (size_t)64 * DM + kt);

        __syncthreads();  // previous tile's compute done before overwrite
        As[lc+0][lr] = a0.x; As[lc+1][lr] = a0.y; As[lc+2][lr] = a0.z; As[lc+3][lr] = a0.w;
        As[lc+0][lr+64] = a1.x; As[lc+1][lr+64] = a1.y; As[lc+2][lr+64] = a1.z; As[lc+3][lr+64] = a1.w;
        Bs[lc+0][lr] = b0.x; Bs[lc+1][lr] = b0.y; Bs[lc+2][lr] = b0.z; Bs[lc+3][lr] = b0.w;
        Bs[lc+0][lr+64] = b1.x; Bs[lc+1][lr+64] = b1.y; Bs[lc+2][lr+64] = b1.z; Bs[lc+3][lr+64] = b1.w;
        __syncthreads();

        #pragma unroll
        for (int k = 0; k < 16; k++) {
            float4 av0 = *(const float4*)&As[k][ty * 8];
            float4 av1 = *(const float4*)&As[k][ty * 8 + 4];
            float4 bv0 = *(const float4*)&Bs[k][tx * 8];
            float4 bv1 = *(const float4*)&Bs[k][tx * 8 + 4];
            float a[8] = {av0.x, av0.y, av0.z, av0.w, av1.x, av1.y, av1.z, av1.w};
            float b[8] = {bv0.x, bv0.y, bv0.z, bv0.w, bv1.x, bv1.y, bv1.z, bv1.w};
            #pragma unroll
            for (int i = 0; i < 8; i++)
                #pragma unroll
                for (int j = 0; j < 8; j++)
                    acc[i][j] = fmaf(a[i], b[j], acc[i][j]);
        }
    }
}

// ---------------------------------------------------------------------------
// QKV projection: y = x @ W^T, scattered into head layout.
// Q,K stored transposed [bh][d][s]; V stored [bh][s][d].
// grid (DM/128, MROWS/128, 3)
// ---------------------------------------------------------------------------
__global__ __launch_bounds__(256, 2)
void qkv_kernel(const float* __restrict__ X,
                const float* __restrict__ Wq,
                const float* __restrict__ Wk,
                const float* __restrict__ Wv)
{
    __shared__ float As[16][128];
    __shared__ float Bs[16][128];

    const float* W = (blockIdx.z == 0) ? Wq : (blockIdx.z == 1) ? Wk : Wv;
    const int m0 = blockIdx.y * 128;
    const int n0 = blockIdx.x * 128;

    float acc[8][8];
    #pragma unroll
    for (int i = 0; i < 8; i++)
        #pragma unroll
        for (int j = 0; j < 8; j++) acc[i][j] = 0.f;

    gemm_mainloop(X, W, m0, n0, acc, As, Bs);

    const int tx = threadIdx.x & 15;
    const int ty = threadIdx.x >> 4;
    #pragma unroll
    for (int i = 0; i < 8; i++) {
        int m = m0 + ty * 8 + i;
        int b = m >> 11, s = m & 2047;
        #pragma unroll
        for (int j = 0; j < 8; j++) {
            int n  = n0 + tx * 8 + j;
            int h  = n >> 6, d = n & 63;
            int bh = b * HEADS + h;
            float v = acc[i][j];
            if (blockIdx.z == 0)
                g_Qt[((size_t)bh * HD + d) * S_LEN + s] = v;
            else if (blockIdx.z == 1)
                g_Kt[((size_t)bh * HD + d) * S_LEN + s] = v;
            else
                g_V[((size_t)bh * S_LEN + s) * HD + d] = v;
        }
    }
}

// ---------------------------------------------------------------------------
// Output projection: out = ctx @ Wo^T, plain row-major store into d_out.
// grid (DM/128, MROWS/128)
// ---------------------------------------------------------------------------
__global__ __launch_bounds__(256, 2)
void proj_kernel(const float* __restrict__ Wo, float* __restrict__ Out)
{
    __shared__ float As[16][128];
    __shared__ float Bs[16][128];

    const int m0 = blockIdx.y * 128;
    const int n0 = blockIdx.x * 128;

    float acc[8][8];
    #pragma unroll
    for (int i = 0; i < 8; i++)
        #pragma unroll
        for (int j = 0; j < 8; j++) acc[i][j] = 0.f;

    gemm_mainloop(g_ctx, Wo, m0, n0, acc, As, Bs);

    const int tx = threadIdx.x & 15;
    const int ty = threadIdx.x >> 4;
    #pragma unroll
    for (int i = 0; i < 8; i++) {
        float4 c0 = make_float4(acc[i][0], acc[i][1], acc[i][2], acc[i][3]);
        float4 c1 = make_float4(acc[i][4], acc[i][5], acc[i][6], acc[i][7]);
        float* p = Out + (size_t)(m0 + ty * 8 + i) * DM + n0 + tx * 8;
        *(float4*)(p)     = c0;
        *(float4*)(p + 4) = c1;
    }
}

// ---------------------------------------------------------------------------
// Attention: one CTA = 128 query rows of one (b,h).
// Streams 16 key tiles of 128: S = Q K^T, P = exp(S*scale) (no max-sub; scores
// bounded ~|6| << 88), writes unnormalized P to attn_weights region, keeps
// rowsums, accumulates P@V. Epilogue normalizes context and stores 1/rowsum.
// grid (S/128, BH), 256 threads, 160 KB dynamic smem.
// ---------------------------------------------------------------------------
#define ATTN_SMEM_FLOATS (64*128 + 64*128 + 128*64 + 128*128)
#define ATTN_SMEM_BYTES  (ATTN_SMEM_FLOATS * 4)

__global__ __launch_bounds__(256, 1)
void attn_kernel(float* __restrict__ attnW)
{
    extern __shared__ float sm[];
    float* Qs = sm;                       // [64][128]  Q^T tile
    float* Ks = sm + 64 * 128;            // [64][128]  K^T tile
    float* Vs = sm + 2 * 64 * 128;        // [128][64]  V tile
    float* Ps = sm + 2 * 64 * 128 + 128 * 64;  // [128][128] exp(scores)

    const int tid = threadIdx.x;
    const int tx  = tid & 15;
    const int ty  = tid >> 4;
    const int bh  = blockIdx.y;
    const int q0  = blockIdx.x * 128;

    const float* Qg = g_Qt + (size_t)bh * HD * S_LEN;
    const float* Kg = g_Kt + (size_t)bh * HD * S_LEN;
    const float* Vg = g_V  + (size_t)bh * S_LEN * HD;
    float* Wbase = attnW + ((size_t)bh * S_LEN + q0) * S_LEN;

    // Q tile load: [bh][d][q0..q0+128), coalesced, conflict-free
    for (int i = tid; i < 64 * 32; i += 256) {
        int d = i >> 5, m4 = i & 31;
        ((float4*)Qs)[d * 32 + m4] = ((const float4*)Qg)[d * 512 + (q0 >> 2) + m4];
    }

    float oacc[8][4];
    float rs[8];
    #pragma unroll
    for (int i = 0; i < 8; i++) {
        rs[i] = 0.f;
        #pragma unroll
        for (int j = 0; j < 4; j++) oacc[i][j] = 0.f;
    }

    for (int kt = 0; kt < 16; kt++) {
        const int k0 = kt * 128;
        __syncthreads();  // previous iter's AV reads of Ps/Vs done

        for (int i = tid; i < 64 * 32; i += 256) {
            int d = i >> 5, m4 = i & 31;
            ((float4*)Ks)[d * 32 + m4] = ((const float4*)Kg)[d * 512 + (k0 >> 2) + m4];
        }
        for (int i = tid; i < 128 * 16; i += 256) {
            int n = i >> 4, d4 = i & 15;
            ((float4*)Vs)[n * 16 + d4] = ((const float4*)Vg)[(size_t)(k0 + n) * 16 + d4];
        }
        __syncthreads();

        // scores: 8x8 per thread over d=0..63
        float sacc[8][8];
        #pragma unroll
        for (int i = 0; i < 8; i++)
            #pragma unroll
            for (int j = 0; j < 8; j++) sacc[i][j] = 0.f;

        #pragma unroll 8
        for (int d = 0; d < 64; d++) {
            float4 a0 = *(const float4*)&Qs[d * 128 + ty * 8];
            float4 a1 = *(const float4*)&Qs[d * 128 + ty * 8 + 4];
            float4 b0 = *(const float4*)&Ks[d * 128 + tx * 8];
            float4 b1 = *(const float4*)&Ks[d * 128 + tx * 8 + 4];
            float a[8] = {a0.x, a0.y, a0.z, a0.w, a1.x, a1.y, a1.z, a1.w};
            float b[8] = {b0.x, b0.y, b0.z, b0.w, b1.x, b1.y, b1.z, b1.w};
            #pragma unroll
            for (int i = 0; i < 8; i++)
                #pragma unroll
                for (int j = 0; j < 8; j++)
                    sacc[i][j] = fmaf(a[i], b[j], sacc[i][j]);
        }

        // exp + rowsum + store (gmem unnormalized, smem for AV)
        #pragma unroll
        for (int i = 0; i < 8; i++) {
            float r = 0.f;
            #pragma unroll
            for (int j = 0; j < 8; j++) {
                float e = __expf(sacc[i][j] * SCALE);
                sacc[i][j] = e;
                r += e;
            }
            // reduce over the 16 tx lanes sharing this ty (xor<=8 stays in half-warp)
            r += __shfl_xor_sync(0xffffffffu, r, 1);
            r += __shfl_xor_sync(0xffffffffu, r, 2);
            r += __shfl_xor_sync(0xffffffffu, r, 4);
            r += __shfl_xor_sync(0xffffffffu, r, 8);
            rs[i] += r;

            float4 e0 = make_float4(sacc[i][0], sacc[i][1], sacc[i][2], sacc[i][3]);
            float4 e1 = make_float4(sacc[i][4], sacc[i][5], sacc[i][6], sacc[i][7]);
            *(float4*)&Ps[(ty * 8 + i) * 128 + tx * 8]     = e0;
            *(float4*)&Ps[(ty * 8 + i) * 128 + tx * 8 + 4] = e1;
            float* wp = Wbase + (size_t)(ty * 8 + i) * S_LEN + k0 + tx * 8;
            *(float4*)(wp)     = e0;
            *(float4*)(wp + 4) = e1;
        }
        __syncthreads();  // Ps visible

        // O += P @ V : 8 rows x 4 cols per thread
        #pragma unroll 4
        for (int n = 0; n < 128; n++) {
            float4 bv = *(const float4*)&Vs[n * 64 + tx * 4];
            #pragma unroll
            for (int i = 0; i < 8; i++) {
                float a = Ps[(ty * 8 + i) * 128 + n];
                oacc[i][0] = fmaf(a, bv.x, oacc[i][0]);
                oacc[i][1] = fmaf(a, bv.y, oacc[i][1]);
                oacc[i][2] = fmaf(a, bv.z, oacc[i][2]);
                oacc[i][3] = fmaf(a, bv.w, oacc[i][3]);
            }
        }
    }

    // epilogue: normalize context, store inverse rowsums
    const int b = bh >> 4;
    const int h = bh & 15;
    #pragma unroll
    for (int i = 0; i < 8; i++) {
        float inv = 1.0f / rs[i];
        int s = q0 + ty * 8 + i;
        float4 o = make_float4(oacc[i][0] * inv, oacc[i][1] * inv,
                               oacc[i][2] * inv, oacc[i][3] * inv);
        *(float4*)&g_ctx[((size_t)b * S_LEN + s) * DM + h * 64 + tx * 4] = o;
        if (tx == 0) g_inv[bh * S_LEN + s] = inv;
    }
}

// ---------------------------------------------------------------------------
// Normalize attn_weights in place: w *= 1/rowsum  (HBM-bound, float4 stride)
// ---------------------------------------------------------------------------
__global__ void norm_kernel(float* __restrict__ attnW)
{
    const size_t total  = (size_t)BH * S_LEN * (S_LEN / 4);  // float4 count
    const size_t stride = (size_t)gridDim.x * blockDim.x;
    for (size_t i = (size_t)blockIdx.x * blockDim.x + threadIdx.x; i < total; i += stride) {
        float inv = g_inv[i >> 9];  // 512 float4 per (b,h,q) row
        float4 w = ((float4*)attnW)[i];
        w.x *= inv; w.y *= inv; w.z *= inv; w.w *= inv;
        ((float4*)attnW)[i] = w;
    }
}

// ---------------------------------------------------------------------------
// Launcher
// ---------------------------------------------------------------------------
extern "C" void kernel_launch(void* const* d_in, const int* in_sizes, int n_in,
                              void* d_out, int out_size)
{
    const float* x  = (const float*)d_in[0];
    const float* Wq = (const float*)d_in[1];
    const float* Wk = (const float*)d_in[2];
    const float* Wv = (const float*)d_in[3];
    const float* Wo = (const float*)d_in[4];

    float* out   = (float*)d_out;
    float* attnW = out + (size_t)MROWS * DM;  // [B,H,S,S] region after [B,S,D]

    cudaFuncSetAttribute(attn_kernel,
                         cudaFuncAttributeMaxDynamicSharedMemorySize,
                         ATTN_SMEM_BYTES);

    dim3 gq(DM / 128, MROWS / 128, 3);
    qkv_kernel<<<gq, 256>>>(x, Wq, Wk, Wv);

    dim3 ga(S_LEN / 128, BH);
    attn_kernel<<<ga, 256, ATTN_SMEM_BYTES>>>(attnW);

    norm_kernel<<<1184, 256>>>(attnW);

    dim3 gp(DM / 128, MROWS / 128);
    proj_kernel<<<gp, 256>>>(Wo, out);
}

// round 7
// speedup vs baseline: 1.3397x; 1.3397x over previous
#include <cuda_runtime.h>
#include <cuda_bf16.h>
#include <cstdint>

// Problem constants
#define S_LEN 2048
#define BATCH 2
#define HEADS 16
#define HD    64
#define DM    1024
#define BH    (BATCH*HEADS)     // 32
#define MROWS (BATCH*S_LEN)     // 4096
#define SCALE 0.125f            // 1/sqrt(64)

// ---------------------------------------------------------------------------
// Scratch (no allocation allowed -> __device__ globals)
// ---------------------------------------------------------------------------
__device__ float g_Qt [(size_t)BH * HD * S_LEN];   // [bh][d][s]
__device__ float g_Kt [(size_t)BH * HD * S_LEN];   // [bh][d][s]
__device__ float g_V  [(size_t)BH * S_LEN * HD];   // [bh][s][d]
__device__ float g_ctx[(size_t)MROWS * DM];        // attention context
__device__ float g_inv[BH * S_LEN];                // 1/rowsum for normalize pass

// ---------------------------------------------------------------------------
// sm_80-compatible tensor-core primitives (compile clean under compute_103)
// ---------------------------------------------------------------------------
__device__ __forceinline__ uint32_t smem_to_u32(const void* p) {
    uint32_t addr;
    asm("{ .reg .u64 tmp; cvta.to.shared.u64 tmp, %1; cvt.u32.u64 %0, tmp; }"
        : "=r"(addr) : "l"(p));
    return addr;
}

__device__ __forceinline__ void ldmx4(uint32_t (&r)[4], uint32_t addr) {
    asm volatile("ldmatrix.sync.aligned.m8n8.x4.shared.b16 {%0,%1,%2,%3}, [%4];"
        : "=r"(r[0]), "=r"(r[1]), "=r"(r[2]), "=r"(r[3]) : "r"(addr));
}
__device__ __forceinline__ void ldmx2(uint32_t (&r)[2], uint32_t addr) {
    asm volatile("ldmatrix.sync.aligned.m8n8.x2.shared.b16 {%0,%1}, [%2];"
        : "=r"(r[0]), "=r"(r[1]) : "r"(addr));
}
__device__ __forceinline__ void mma16816(float (&c)[4],
                                         const uint32_t (&a)[4],
                                         const uint32_t (&b)[2]) {
    asm volatile(
        "mma.sync.aligned.m16n8k16.row.col.f32.bf16.bf16.f32 "
        "{%0,%1,%2,%3}, {%4,%5,%6,%7}, {%8,%9}, {%0,%1,%2,%3};"
        : "+f"(c[0]), "+f"(c[1]), "+f"(c[2]), "+f"(c[3])
        : "r"(a[0]), "r"(a[1]), "r"(a[2]), "r"(a[3]), "r"(b[0]), "r"(b[1]));
}

#define SWZ(off) ((off) ^ (((off) >> 3) & 0x70))

// fp32 -> (hi, lo) bf16 split, packed pairwise
__device__ __forceinline__ void split2(float a, float b, uint32_t& wh, uint32_t& wl)
{
    __nv_bfloat16 ha = __float2bfloat16(a), hb = __float2bfloat16(b);
    float ra = a - __bfloat162float(ha);
    float rb = b - __bfloat162float(hb);
    __nv_bfloat16 la = __float2bfloat16(ra), lb = __float2bfloat16(rb);
    wh = (uint32_t)__bfloat16_as_ushort(ha) | ((uint32_t)__bfloat16_as_ushort(hb) << 16);
    wl = (uint32_t)__bfloat16_as_ushort(la) | ((uint32_t)__bfloat16_as_ushort(lb) << 16);
}

// ---------------------------------------------------------------------------
// HMMA GEMM mainloop: 128x128 C tile of A[M,1024] @ B[N,1024]^T (both K-major
// fp32 in gmem). 256 threads = 8 warps, warp tile 64x32. 3-MMA bf16 split.
// smem: Ah/Al/Bh/Bl [128][64] bf16 (16KB each, SWZ swizzled), 64KB total.
// acc[mi][ni][4] per thread.
// ---------------------------------------------------------------------------
__device__ __forceinline__ void hmma_mainloop(
    const float* __restrict__ A, const float* __restrict__ B,
    int m0, int n0, char* sm, float (&acc)[4][4][4])
{
    const int tid  = threadIdx.x;
    const int wid  = tid >> 5;
    const int lane = tid & 31;
    const int wm   = (wid & 1) * 64;    // warp M offset
    const int wn   = (wid >> 1) * 32;   // warp N offset
    const int lane8 = tid & 7;          // 8-float column group
    const int rgrp  = (tid >> 3) & 31;  // base row 0..31

    const uint32_t sAh = smem_to_u32(sm);
    const uint32_t sAl = sAh + 16384;
    const uint32_t sBh = sAh + 32768;
    const uint32_t sBl = sAh + 49152;

    // per-thread constant pieces of fragment addresses
    const uint32_t a_row_lo = (lane & 15);       // row within 16-row block
    const uint32_t a_kb     = (lane >> 4) * 16;  // 16B k-half
    const uint32_t b_row_lo = (lane & 7);
    const uint32_t b_kb     = ((lane >> 3) & 1) * 16;

    for (int kc = 0; kc < 16; kc++) {
        // ---- load fp32, split to bf16 hi/lo, store swizzled ----
        const float* Ap = A + (size_t)(m0 + rgrp) * DM + kc * 64 + lane8 * 8;
        const float* Bp = B + (size_t)(n0 + rgrp) * DM + kc * 64 + lane8 * 8;
        #pragma unroll
        for (int rr = 0; rr < 4; rr++) {
            float4 va0 = *(const float4*)(Ap + (size_t)rr * 32 * DM);
            float4 va1 = *(const float4*)(Ap + (size_t)rr * 32 * DM + 4);
            float4 vb0 = *(const float4*)(Bp + (size_t)rr * 32 * DM);
            float4 vb1 = *(const float4*)(Bp + (size_t)rr * 32 * DM + 4);
            uint32_t off = (uint32_t)(rgrp + rr * 32) * 128 + lane8 * 16;
            uint32_t sw  = SWZ(off);
            uint32_t h0,l0,h1,l1,h2,l2,h3,l3;
            split2(va0.x, va0.y, h0, l0); split2(va0.z, va0.w, h1, l1);
            split2(va1.x, va1.y, h2, l2); split2(va1.z, va1.w, h3, l3);
            *(uint4*)(sm +         sw) = make_uint4(h0, h1, h2, h3);
            *(uint4*)(sm + 16384 + sw) = make_uint4(l0, l1, l2, l3);
            split2(vb0.x, vb0.y, h0, l0); split2(vb0.z, vb0.w, h1, l1);
            split2(vb1.x, vb1.y, h2, l2); split2(vb1.z, vb1.w, h3, l3);
            *(uint4*)(sm + 32768 + sw) = make_uint4(h0, h1, h2, h3);
            *(uint4*)(sm + 49152 + sw) = make_uint4(l0, l1, l2, l3);
        }
        __syncthreads();

        // ---- compute: 4 k-steps of 16 ----
        #pragma unroll
        for (int ks = 0; ks < 4; ks++) {
            uint32_t ah[4][4], al[4][4];
            #pragma unroll
            for (int mi = 0; mi < 4; mi++) {
                uint32_t row = wm + mi * 16 + a_row_lo;
                uint32_t off = row * 128 + ks * 32 + a_kb;
                uint32_t sw  = SWZ(off);
                ldmx4(ah[mi], sAh + sw);
                ldmx4(al[mi], sAl + sw);
            }
            #pragma unroll
            for (int ni = 0; ni < 4; ni++) {
                uint32_t row = wn + ni * 8 + b_row_lo;
                uint32_t off = row * 128 + ks * 32 + b_kb;
                uint32_t sw  = SWZ(off);
                uint32_t bh[2], bl[2];
                ldmx2(bh, sBh + sw);
                ldmx2(bl, sBl + sw);
                #pragma unroll
                for (int mi = 0; mi < 4; mi++) {
                    mma16816(acc[mi][ni], ah[mi], bh);
                    mma16816(acc[mi][ni], ah[mi], bl);
                    mma16816(acc[mi][ni], al[mi], bh);
                }
            }
        }
        __syncthreads();
    }
}

// ---------------------------------------------------------------------------
// QKV projection: y = x @ W^T scattered into head layouts.
// grid (8 n-tiles, 32 m-tiles, 3), 256 threads, 64KB smem.
// ---------------------------------------------------------------------------
__global__ __launch_bounds__(256, 2)
void qkv_kernel(const float* __restrict__ X,
                const float* __restrict__ Wq,
                const float* __restrict__ Wk,
                const float* __restrict__ Wv)
{
    extern __shared__ char sm[];
    const float* W = (blockIdx.z == 0) ? Wq : (blockIdx.z == 1) ? Wk : Wv;
    const int m0 = blockIdx.y * 128;
    const int n0 = blockIdx.x * 128;

    float acc[4][4][4];
    #pragma unroll
    for (int i = 0; i < 4; i++)
        #pragma unroll
        for (int j = 0; j < 4; j++)
            #pragma unroll
            for (int r = 0; r < 4; r++) acc[i][j][r] = 0.f;

    hmma_mainloop(X, W, m0, n0, sm, acc);

    const int wid  = threadIdx.x >> 5;
    const int lane = threadIdx.x & 31;
    const int wm   = (wid & 1) * 64;
    const int wn   = (wid >> 1) * 32;
    const int gr   = lane >> 2;
    const int gc   = (lane & 3) * 2;

    #pragma unroll
    for (int mi = 0; mi < 4; mi++)
        #pragma unroll
        for (int half = 0; half < 2; half++) {
            int m = m0 + wm + mi * 16 + gr + half * 8;
            int bb = m >> 11, s = m & 2047;
            #pragma unroll
            for (int ni = 0; ni < 4; ni++)
                #pragma unroll
                for (int e = 0; e < 2; e++) {
                    int n = n0 + wn + ni * 8 + gc + e;
                    int h = n >> 6, d = n & 63;
                    int bh_ = bb * HEADS + h;
                    float v = acc[mi][ni][half * 2 + e];
                    if (blockIdx.z == 0)
                        g_Qt[((size_t)bh_ * HD + d) * S_LEN + s] = v;
                    else if (blockIdx.z == 1)
                        g_Kt[((size_t)bh_ * HD + d) * S_LEN + s] = v;
                    else
                        g_V[((size_t)bh_ * S_LEN + s) * HD + d] = v;
                }
        }
}

// ---------------------------------------------------------------------------
// Output projection: out = ctx @ Wo^T. grid (8, 32), 256 threads, 64KB smem.
// ---------------------------------------------------------------------------
__global__ __launch_bounds__(256, 2)
void proj_kernel(const float* __restrict__ Wo, float* __restrict__ Out)
{
    extern __shared__ char sm[];
    const int m0 = blockIdx.y * 128;
    const int n0 = blockIdx.x * 128;

    float acc[4][4][4];
    #pragma unroll
    for (int i = 0; i < 4; i++)
        #pragma unroll
        for (int j = 0; j < 4; j++)
            #pragma unroll
            for (int r = 0; r < 4; r++) acc[i][j][r] = 0.f;

    hmma_mainloop(g_ctx, Wo, m0, n0, sm, acc);

    const int wid  = threadIdx.x >> 5;
    const int lane = threadIdx.x & 31;
    const int wm   = (wid & 1) * 64;
    const int wn   = (wid >> 1) * 32;
    const int gr   = lane >> 2;
    const int gc   = (lane & 3) * 2;

    #pragma unroll
    for (int mi = 0; mi < 4; mi++)
        #pragma unroll
        for (int half = 0; half < 2; half++) {
            int m = m0 + wm + mi * 16 + gr + half * 8;
            float* row = Out + (size_t)m * DM + n0 + wn + gc;
            #pragma unroll
            for (int ni = 0; ni < 4; ni++) {
                float2 v = make_float2(acc[mi][ni][half * 2],
                                       acc[mi][ni][half * 2 + 1]);
                *(float2*)(row + ni * 8) = v;
            }
        }
}

// ---------------------------------------------------------------------------
// Attention (unchanged from passing round): one CTA = 128 queries of one (b,h).
// ---------------------------------------------------------------------------
#define ATTN_SMEM_FLOATS (64*128 + 64*128 + 128*64 + 128*128)
#define ATTN_SMEM_BYTES  (ATTN_SMEM_FLOATS * 4)

__global__ __launch_bounds__(256, 1)
void attn_kernel(float* __restrict__ attnW)
{
    extern __shared__ float smf[];
    float* Qs = smf;                       // [64][128]
    float* Ks = smf + 64 * 128;            // [64][128]
    float* Vs = smf + 2 * 64 * 128;        // [128][64]
    float* Ps = smf + 2 * 64 * 128 + 128 * 64;  // [128][128]

    const int tid = threadIdx.x;
    const int tx  = tid & 15;
    const int ty  = tid >> 4;
    const int bh  = blockIdx.y;
    const int q0  = blockIdx.x * 128;

    const float* Qg = g_Qt + (size_t)bh * HD * S_LEN;
    const float* Kg = g_Kt + (size_t)bh * HD * S_LEN;
    const float* Vg = g_V  + (size_t)bh * S_LEN * HD;
    float* Wbase = attnW + ((size_t)bh * S_LEN + q0) * S_LEN;

    for (int i = tid; i < 64 * 32; i += 256) {
        int d = i >> 5, m4 = i & 31;
        ((float4*)Qs)[d * 32 + m4] = ((const float4*)Qg)[d * 512 + (q0 >> 2) + m4];
    }

    float oacc[8][4];
    float rs[8];
    #pragma unroll
    for (int i = 0; i < 8; i++) {
        rs[i] = 0.f;
        #pragma unroll
        for (int j = 0; j < 4; j++) oacc[i][j] = 0.f;
    }

    for (int kt = 0; kt < 16; kt++) {
        const int k0 = kt * 128;
        __syncthreads();

        for (int i = tid; i < 64 * 32; i += 256) {
            int d = i >> 5, m4 = i & 31;
            ((float4*)Ks)[d * 32 + m4] = ((const float4*)Kg)[d * 512 + (k0 >> 2) + m4];
        }
        for (int i = tid; i < 128 * 16; i += 256) {
            int n = i >> 4, d4 = i & 15;
            ((float4*)Vs)[n * 16 + d4] = ((const float4*)Vg)[(size_t)(k0 + n) * 16 + d4];
        }
        __syncthreads();

        float sacc[8][8];
        #pragma unroll
        for (int i = 0; i < 8; i++)
            #pragma unroll
            for (int j = 0; j < 8; j++) sacc[i][j] = 0.f;

        #pragma unroll 8
        for (int d = 0; d < 64; d++) {
            float4 a0 = *(const float4*)&Qs[d * 128 + ty * 8];
            float4 a1 = *(const float4*)&Qs[d * 128 + ty * 8 + 4];
            float4 b0 = *(const float4*)&Ks[d * 128 + tx * 8];
            float4 b1 = *(const float4*)&Ks[d * 128 + tx * 8 + 4];
            float a[8] = {a0.x, a0.y, a0.z, a0.w, a1.x, a1.y, a1.z, a1.w};
            float b[8] = {b0.x, b0.y, b0.z, b0.w, b1.x, b1.y, b1.z, b1.w};
            #pragma unroll
            for (int i = 0; i < 8; i++)
                #pragma unroll
                for (int j = 0; j < 8; j++)
                    sacc[i][j] = fmaf(a[i], b[j], sacc[i][j]);
        }

        #pragma unroll
        for (int i = 0; i < 8; i++) {
            float r = 0.f;
            #pragma unroll
            for (int j = 0; j < 8; j++) {
                float e = __expf(sacc[i][j] * SCALE);
                sacc[i][j] = e;
                r += e;
            }
            r += __shfl_xor_sync(0xffffffffu, r, 1);
            r += __shfl_xor_sync(0xffffffffu, r, 2);
            r += __shfl_xor_sync(0xffffffffu, r, 4);
            r += __shfl_xor_sync(0xffffffffu, r, 8);
            rs[i] += r;

            float4 e0 = make_float4(sacc[i][0], sacc[i][1], sacc[i][2], sacc[i][3]);
            float4 e1 = make_float4(sacc[i][4], sacc[i][5], sacc[i][6], sacc[i][7]);
            *(float4*)&Ps[(ty * 8 + i) * 128 + tx * 8]     = e0;
            *(float4*)&Ps[(ty * 8 + i) * 128 + tx * 8 + 4] = e1;
            float* wp = Wbase + (size_t)(ty * 8 + i) * S_LEN + k0 + tx * 8;
            *(float4*)(wp)     = e0;
            *(float4*)(wp + 4) = e1;
        }
        __syncthreads();

        #pragma unroll 4
        for (int n = 0; n < 128; n++) {
            float4 bv = *(const float4*)&Vs[n * 64 + tx * 4];
            #pragma unroll
            for (int i = 0; i < 8; i++) {
                float a = Ps[(ty * 8 + i) * 128 + n];
                oacc[i][0] = fmaf(a, bv.x, oacc[i][0]);
                oacc[i][1] = fmaf(a, bv.y, oacc[i][1]);
                oacc[i][2] = fmaf(a, bv.z, oacc[i][2]);
                oacc[i][3] = fmaf(a, bv.w, oacc[i][3]);
            }
        }
    }

    const int b = bh >> 4;
    const int h = bh & 15;
    #pragma unroll
    for (int i = 0; i < 8; i++) {
        float inv = 1.0f / rs[i];
        int s = q0 + ty * 8 + i;
        float4 o = make_float4(oacc[i][0] * inv, oacc[i][1] * inv,
                               oacc[i][2] * inv, oacc[i][3] * inv);
        *(float4*)&g_ctx[((size_t)b * S_LEN + s) * DM + h * 64 + tx * 4] = o;
        if (tx == 0) g_inv[bh * S_LEN + s] = inv;
    }
}

// ---------------------------------------------------------------------------
// Normalize attn_weights in place (HBM-bound)
// ---------------------------------------------------------------------------
__global__ void norm_kernel(float* __restrict__ attnW)
{
    const size_t total  = (size_t)BH * S_LEN * (S_LEN / 4);
    const size_t stride = (size_t)gridDim.x * blockDim.x;
    for (size_t i = (size_t)blockIdx.x * blockDim.x + threadIdx.x; i < total; i += stride) {
        float inv = g_inv[i >> 9];
        float4 w = ((float4*)attnW)[i];
        w.x *= inv; w.y *= inv; w.z *= inv; w.w *= inv;
        ((float4*)attnW)[i] = w;
    }
}

// ---------------------------------------------------------------------------
// Launcher
// ---------------------------------------------------------------------------
#define GEMM_SMEM_BYTES 65536

extern "C" void kernel_launch(void* const* d_in, const int* in_sizes, int n_in,
                              void* d_out, int out_size)
{
    const float* x  = (const float*)d_in[0];
    const float* Wq = (const float*)d_in[1];
    const float* Wk = (const float*)d_in[2];
    const float* Wv = (const float*)d_in[3];
    const float* Wo = (const float*)d_in[4];

    float* out   = (float*)d_out;
    float* attnW = out + (size_t)MROWS * DM;

    cudaFuncSetAttribute(qkv_kernel,
                         cudaFuncAttributeMaxDynamicSharedMemorySize, GEMM_SMEM_BYTES);
    cudaFuncSetAttribute(proj_kernel,
                         cudaFuncAttributeMaxDynamicSharedMemorySize, GEMM_SMEM_BYTES);
    cudaFuncSetAttribute(attn_kernel,
                         cudaFuncAttributeMaxDynamicSharedMemorySize, ATTN_SMEM_BYTES);

    dim3 gq(DM / 128, MROWS / 128, 3);
    qkv_kernel<<<gq, 256, GEMM_SMEM_BYTES>>>(x, Wq, Wk, Wv);

    dim3 ga(S_LEN / 128, BH);
    attn_kernel<<<ga, 256, ATTN_SMEM_BYTES>>>(attnW);

    norm_kernel<<<1184, 256>>>(attnW);

    dim3 gp(DM / 128, MROWS / 128);
    proj_kernel<<<gp, 256, GEMM_SMEM_BYTES>>>(Wo, out);
}

// round 8
// speedup vs baseline: 2.2628x; 1.6891x over previous
#include <cuda_runtime.h>
#include <cuda_bf16.h>
#include <cstdint>

// Problem constants
#define S_LEN 2048
#define BATCH 2
#define HEADS 16
#define HD    64
#define DM    1024
#define BH    (BATCH*HEADS)     // 32
#define MROWS (BATCH*S_LEN)     // 4096
#define SCALE 0.125f            // 1/sqrt(64)

// ---------------------------------------------------------------------------
// Scratch: Q/K/V stored as pre-split bf16 hi/lo planes, [bh][s][d]
// ---------------------------------------------------------------------------
__device__ __nv_bfloat16 g_Qh[(size_t)BH * S_LEN * HD];
__device__ __nv_bfloat16 g_Ql[(size_t)BH * S_LEN * HD];
__device__ __nv_bfloat16 g_Kh[(size_t)BH * S_LEN * HD];
__device__ __nv_bfloat16 g_Kl[(size_t)BH * S_LEN * HD];
__device__ __nv_bfloat16 g_Vh[(size_t)BH * S_LEN * HD];
__device__ __nv_bfloat16 g_Vl[(size_t)BH * S_LEN * HD];
__device__ float g_ctx[(size_t)MROWS * DM];        // attention context fp32
__device__ float g_inv[BH * S_LEN];                // 1/rowsum

// ---------------------------------------------------------------------------
// sm_80-compatible tensor-core primitives
// ---------------------------------------------------------------------------
__device__ __forceinline__ uint32_t smem_to_u32(const void* p) {
    uint32_t addr;
    asm("{ .reg .u64 tmp; cvta.to.shared.u64 tmp, %1; cvt.u32.u64 %0, tmp; }"
        : "=r"(addr) : "l"(p));
    return addr;
}
__device__ __forceinline__ void ldmx4(uint32_t (&r)[4], uint32_t addr) {
    asm volatile("ldmatrix.sync.aligned.m8n8.x4.shared.b16 {%0,%1,%2,%3}, [%4];"
        : "=r"(r[0]), "=r"(r[1]), "=r"(r[2]), "=r"(r[3]) : "r"(addr));
}
__device__ __forceinline__ void ldmx2(uint32_t (&r)[2], uint32_t addr) {
    asm volatile("ldmatrix.sync.aligned.m8n8.x2.shared.b16 {%0,%1}, [%2];"
        : "=r"(r[0]), "=r"(r[1]) : "r"(addr));
}
__device__ __forceinline__ void ldmx2t(uint32_t (&r)[2], uint32_t addr) {
    asm volatile("ldmatrix.sync.aligned.m8n8.x2.trans.shared.b16 {%0,%1}, [%2];"
        : "=r"(r[0]), "=r"(r[1]) : "r"(addr));
}
__device__ __forceinline__ void mma16816(float (&c)[4],
                                         const uint32_t (&a)[4],
                                         const uint32_t (&b)[2]) {
    asm volatile(
        "mma.sync.aligned.m16n8k16.row.col.f32.bf16.bf16.f32 "
        "{%0,%1,%2,%3}, {%4,%5,%6,%7}, {%8,%9}, {%0,%1,%2,%3};"
        : "+f"(c[0]), "+f"(c[1]), "+f"(c[2]), "+f"(c[3])
        : "r"(a[0]), "r"(a[1]), "r"(a[2]), "r"(a[3]), "r"(b[0]), "r"(b[1]));
}

#define SWZ(off) ((off) ^ (((off) >> 3) & 0x70))

// fp32 -> (hi, lo) bf16 split, packed pairwise
__device__ __forceinline__ void split2(float a, float b, uint32_t& wh, uint32_t& wl)
{
    __nv_bfloat16 ha = __float2bfloat16(a), hb = __float2bfloat16(b);
    float ra = a - __bfloat162float(ha);
    float rb = b - __bfloat162float(hb);
    __nv_bfloat16 la = __float2bfloat16(ra), lb = __float2bfloat16(rb);
    wh = (uint32_t)__bfloat16_as_ushort(ha) | ((uint32_t)__bfloat16_as_ushort(hb) << 16);
    wl = (uint32_t)__bfloat16_as_ushort(la) | ((uint32_t)__bfloat16_as_ushort(lb) << 16);
}

// ---------------------------------------------------------------------------
// HMMA GEMM mainloop (unchanged from passing round): 128x128 C tile of
// A[M,1024] @ B[N,1024]^T, 256 threads, warp tile 64x32, 3-MMA bf16 split.
// ---------------------------------------------------------------------------
__device__ __forceinline__ void hmma_mainloop(
    const float* __restrict__ A, const float* __restrict__ B,
    int m0, int n0, char* sm, float (&acc)[4][4][4])
{
    const int tid  = threadIdx.x;
    const int wid  = tid >> 5;
    const int lane = tid & 31;
    const int wm   = (wid & 1) * 64;
    const int wn   = (wid >> 1) * 32;
    const int lane8 = tid & 7;
    const int rgrp  = (tid >> 3) & 31;

    const uint32_t sAh = smem_to_u32(sm);
    const uint32_t sAl = sAh + 16384;
    const uint32_t sBh = sAh + 32768;
    const uint32_t sBl = sAh + 49152;

    const uint32_t a_row_lo = (lane & 15);
    const uint32_t a_kb     = (lane >> 4) * 16;
    const uint32_t b_row_lo = (lane & 7);
    const uint32_t b_kb     = ((lane >> 3) & 1) * 16;

    for (int kc = 0; kc < 16; kc++) {
        const float* Ap = A + (size_t)(m0 + rgrp) * DM + kc * 64 + lane8 * 8;
        const float* Bp = B + (size_t)(n0 + rgrp) * DM + kc * 64 + lane8 * 8;
        #pragma unroll
        for (int rr = 0; rr < 4; rr++) {
            float4 va0 = *(const float4*)(Ap + (size_t)rr * 32 * DM);
            float4 va1 = *(const float4*)(Ap + (size_t)rr * 32 * DM + 4);
            float4 vb0 = *(const float4*)(Bp + (size_t)rr * 32 * DM);
            float4 vb1 = *(const float4*)(Bp + (size_t)rr * 32 * DM + 4);
            uint32_t off = (uint32_t)(rgrp + rr * 32) * 128 + lane8 * 16;
            uint32_t sw  = SWZ(off);
            uint32_t h0,l0,h1,l1,h2,l2,h3,l3;
            split2(va0.x, va0.y, h0, l0); split2(va0.z, va0.w, h1, l1);
            split2(va1.x, va1.y, h2, l2); split2(va1.z, va1.w, h3, l3);
            *(uint4*)(sm +         sw) = make_uint4(h0, h1, h2, h3);
            *(uint4*)(sm + 16384 + sw) = make_uint4(l0, l1, l2, l3);
            split2(vb0.x, vb0.y, h0, l0); split2(vb0.z, vb0.w, h1, l1);
            split2(vb1.x, vb1.y, h2, l2); split2(vb1.z, vb1.w, h3, l3);
            *(uint4*)(sm + 32768 + sw) = make_uint4(h0, h1, h2, h3);
            *(uint4*)(sm + 49152 + sw) = make_uint4(l0, l1, l2, l3);
        }
        __syncthreads();

        #pragma unroll
        for (int ks = 0; ks < 4; ks++) {
            uint32_t ah[4][4], al[4][4];
            #pragma unroll
            for (int mi = 0; mi < 4; mi++) {
                uint32_t row = wm + mi * 16 + a_row_lo;
                uint32_t sw  = SWZ(row * 128 + ks * 32 + a_kb);
                ldmx4(ah[mi], sAh + sw);
                ldmx4(al[mi], sAl + sw);
            }
            #pragma unroll
            for (int ni = 0; ni < 4; ni++) {
                uint32_t row = wn + ni * 8 + b_row_lo;
                uint32_t sw  = SWZ(row * 128 + ks * 32 + b_kb);
                uint32_t bh[2], bl[2];
                ldmx2(bh, sBh + sw);
                ldmx2(bl, sBl + sw);
                #pragma unroll
                for (int mi = 0; mi < 4; mi++) {
                    mma16816(acc[mi][ni], ah[mi], bh);
                    mma16816(acc[mi][ni], ah[mi], bl);
                    mma16816(acc[mi][ni], al[mi], bh);
                }
            }
        }
        __syncthreads();
    }
}

// ---------------------------------------------------------------------------
// QKV projection -> pre-split bf16 hi/lo planes [bh][s][d].
// grid (8, 32, 3), 256 threads, 64KB smem.
// ---------------------------------------------------------------------------
__global__ __launch_bounds__(256, 2)
void qkv_kernel(const float* __restrict__ X,
                const float* __restrict__ Wq,
                const float* __restrict__ Wk,
                const float* __restrict__ Wv)
{
    extern __shared__ char sm[];
    const float* W = (blockIdx.z == 0) ? Wq : (blockIdx.z == 1) ? Wk : Wv;
    const int m0 = blockIdx.y * 128;
    const int n0 = blockIdx.x * 128;

    float acc[4][4][4];
    #pragma unroll
    for (int i = 0; i < 4; i++)
        #pragma unroll
        for (int j = 0; j < 4; j++)
            #pragma unroll
            for (int r = 0; r < 4; r++) acc[i][j][r] = 0.f;

    hmma_mainloop(X, W, m0, n0, sm, acc);

    const int wid  = threadIdx.x >> 5;
    const int lane = threadIdx.x & 31;
    const int wm   = (wid & 1) * 64;
    const int wn   = (wid >> 1) * 32;
    const int gr   = lane >> 2;
    const int gc   = (lane & 3) * 2;

    #pragma unroll
    for (int mi = 0; mi < 4; mi++)
        #pragma unroll
        for (int half = 0; half < 2; half++) {
            int m = m0 + wm + mi * 16 + gr + half * 8;
            int bb = m >> 11, s = m & 2047;
            #pragma unroll
            for (int ni = 0; ni < 4; ni++) {
                int n = n0 + wn + ni * 8 + gc;
                int h = n >> 6, d = n & 63;
                size_t idx = ((size_t)(bb * HEADS + h) * S_LEN + s) * HD + d;
                uint32_t hw, lw;
                split2(acc[mi][ni][half * 2], acc[mi][ni][half * 2 + 1], hw, lw);
                if (blockIdx.z == 0) {
                    *(uint32_t*)(g_Qh + idx) = hw;
                    *(uint32_t*)(g_Ql + idx) = lw;
                } else if (blockIdx.z == 1) {
                    *(uint32_t*)(g_Kh + idx) = hw;
                    *(uint32_t*)(g_Kl + idx) = lw;
                } else {
                    *(uint32_t*)(g_Vh + idx) = hw;
                    *(uint32_t*)(g_Vl + idx) = lw;
                }
            }
        }
}

// ---------------------------------------------------------------------------
// Output projection: out = ctx @ Wo^T. grid (8, 32), 256 threads.
// ---------------------------------------------------------------------------
__global__ __launch_bounds__(256, 2)
void proj_kernel(const float* __restrict__ Wo, float* __restrict__ Out)
{
    extern __shared__ char sm[];
    const int m0 = blockIdx.y * 128;
    const int n0 = blockIdx.x * 128;

    float acc[4][4][4];
    #pragma unroll
    for (int i = 0; i < 4; i++)
        #pragma unroll
        for (int j = 0; j < 4; j++)
            #pragma unroll
            for (int r = 0; r < 4; r++) acc[i][j][r] = 0.f;

    hmma_mainloop(g_ctx, Wo, m0, n0, sm, acc);

    const int wid  = threadIdx.x >> 5;
    const int lane = threadIdx.x & 31;
    const int wm   = (wid & 1) * 64;
    const int wn   = (wid >> 1) * 32;
    const int gr   = lane >> 2;
    const int gc   = (lane & 3) * 2;

    #pragma unroll
    for (int mi = 0; mi < 4; mi++)
        #pragma unroll
        for (int half = 0; half < 2; half++) {
            int m = m0 + wm + mi * 16 + gr + half * 8;
            float* row = Out + (size_t)m * DM + n0 + wn + gc;
            #pragma unroll
            for (int ni = 0; ni < 4; ni++)
                *(float2*)(row + ni * 8) = make_float2(acc[mi][ni][half * 2],
                                                       acc[mi][ni][half * 2 + 1]);
        }
}

// ---------------------------------------------------------------------------
// HMMA attention. CTA = 128 queries x one (b,h). 512 threads = 16 warps:
// warp tile 16(q) x 64(k-half); key dim split over 2 warp groups.
// S = QK^T (3-MMA split), P = exp (unnormalized, written to attnW),
// O += P@V (3-MMA split, V via ldmatrix.trans). Epilogue reduces O + rowsums
// across the 2 key halves via smem, normalizes ctx, stores 1/rowsum.
// ---------------------------------------------------------------------------
#define AT_QH   0
#define AT_QL   16384
#define AT_KH   32768
#define AT_KL   49152
#define AT_VH   65536
#define AT_VL   81920
#define AT_OBUF 65536           /* reuse V region after mainloop: f32[128][64] */
#define AT_RS   98304           /* f32[2][128] */
#define AT_SMEM_BYTES (98304 + 1024)

__global__ __launch_bounds__(512, 1)
void attn_kernel(float* __restrict__ attnW)
{
    extern __shared__ char sm[];
    const int tid  = threadIdx.x;
    const int wid  = tid >> 5;
    const int lane = tid & 31;
    const int wq   = wid & 7;       // q block (16 rows)
    const int wk   = wid >> 3;      // key half (64 cols)
    const int bh   = blockIdx.y;
    const int q0   = blockIdx.x * 128;

    const size_t plane = (size_t)bh * S_LEN * HD;

    // ---- load Q tile (once) ----
    {
        const __nv_bfloat16* qh = g_Qh + plane + (size_t)q0 * HD;
        const __nv_bfloat16* ql = g_Ql + plane + (size_t)q0 * HD;
        #pragma unroll
        for (int it = 0; it < 2; it++) {
            int i = tid + it * 512;
            int row = i >> 3, c16 = i & 7;
            uint32_t sw = SWZ((uint32_t)(row * 128 + c16 * 16));
            *(uint4*)(sm + AT_QH + sw) = *(const uint4*)((const char*)(qh + (size_t)row * 64) + c16 * 16);
            *(uint4*)(sm + AT_QL + sw) = *(const uint4*)((const char*)(ql + (size_t)row * 64) + c16 * 16);
        }
    }

    const uint32_t sbase = smem_to_u32(sm);
    const uint32_t a_off = (uint32_t)((wq * 16 + (lane & 15)) * 128 + (lane >> 4) * 16);
    const uint32_t b_row = (uint32_t)(wk * 64 + (lane & 7));
    const uint32_t b_kb  = ((lane >> 3) & 1) * 16;
    const uint32_t v_row = (uint32_t)(wk * 64 + (lane & 15));

    float Oacc[8][4];
    #pragma unroll
    for (int i = 0; i < 8; i++)
        #pragma unroll
        for (int j = 0; j < 4; j++) Oacc[i][j] = 0.f;
    float rs0 = 0.f, rs1 = 0.f;

    for (int kt = 0; kt < 16; kt++) {
        const int k0 = kt * 128;
        __syncthreads();
        {
            const __nv_bfloat16* kh = g_Kh + plane + (size_t)k0 * HD;
            const __nv_bfloat16* kl = g_Kl + plane + (size_t)k0 * HD;
            const __nv_bfloat16* vh = g_Vh + plane + (size_t)k0 * HD;
            const __nv_bfloat16* vl = g_Vl + plane + (size_t)k0 * HD;
            #pragma unroll
            for (int it = 0; it < 2; it++) {
                int i = tid + it * 512;
                int row = i >> 3, c16 = i & 7;
                uint32_t sw = SWZ((uint32_t)(row * 128 + c16 * 16));
                size_t gb = (size_t)row * 64;
                *(uint4*)(sm + AT_KH + sw) = *(const uint4*)((const char*)(kh + gb) + c16 * 16);
                *(uint4*)(sm + AT_KL + sw) = *(const uint4*)((const char*)(kl + gb) + c16 * 16);
                *(uint4*)(sm + AT_VH + sw) = *(const uint4*)((const char*)(vh + gb) + c16 * 16);
                *(uint4*)(sm + AT_VL + sw) = *(const uint4*)((const char*)(vl + gb) + c16 * 16);
            }
        }
        __syncthreads();

        // ---- S = Q K^T (warp: 16q x 64k), 3-MMA split ----
        float Sacc[8][4];
        #pragma unroll
        for (int i = 0; i < 8; i++)
            #pragma unroll
            for (int j = 0; j < 4; j++) Sacc[i][j] = 0.f;

        #pragma unroll
        for (int ks = 0; ks < 4; ks++) {
            uint32_t ah[4], al[4];
            uint32_t qa = SWZ(a_off + ks * 32);
            ldmx4(ah, sbase + AT_QH + qa);
            ldmx4(al, sbase + AT_QL + qa);
            #pragma unroll
            for (int ni = 0; ni < 8; ni++) {
                uint32_t ka = SWZ((b_row + ni * 8) * 128 + ks * 32 + b_kb);
                uint32_t kf[2], klf[2];
                ldmx2(kf,  sbase + AT_KH + ka);
                ldmx2(klf, sbase + AT_KL + ka);
                mma16816(Sacc[ni], ah, kf);
                mma16816(Sacc[ni], ah, klf);
                mma16816(Sacc[ni], al, kf);
            }
        }

        // ---- exp + attnW store + rowsum + repack to A-fragments ----
        uint32_t pah[4][4], pal[4][4];
        float* Wrow = attnW + ((size_t)bh * S_LEN + q0 + wq * 16 + (lane >> 2)) * S_LEN
                    + k0 + wk * 64 + (lane & 3) * 2;
        #pragma unroll
        for (int ni = 0; ni < 8; ni++) {
            float e0 = __expf(Sacc[ni][0] * SCALE);
            float e1 = __expf(Sacc[ni][1] * SCALE);
            float e2 = __expf(Sacc[ni][2] * SCALE);
            float e3 = __expf(Sacc[ni][3] * SCALE);
            rs0 += e0 + e1;
            rs1 += e2 + e3;
            *(float2*)(Wrow + ni * 8)                      = make_float2(e0, e1);
            *(float2*)(Wrow + (size_t)8 * S_LEN + ni * 8)  = make_float2(e2, e3);
            uint32_t h01, l01, h23, l23;
            split2(e0, e1, h01, l01);
            split2(e2, e3, h23, l23);
            int kp = ni >> 1, o = (ni & 1) * 2;
            pah[kp][o] = h01; pah[kp][o + 1] = h23;
            pal[kp][o] = l01; pal[kp][o + 1] = l23;
        }

        // ---- O += P @ V (warp: 16q x 64d over its 64-key half) ----
        #pragma unroll
        for (int kp = 0; kp < 4; kp++) {
            #pragma unroll
            for (int nd = 0; nd < 8; nd++) {
                uint32_t va = SWZ((v_row + kp * 16) * 128 + nd * 16);
                uint32_t vhf[2], vlf[2];
                ldmx2t(vhf, sbase + AT_VH + va);
                ldmx2t(vlf, sbase + AT_VL + va);
                mma16816(Oacc[nd], pah[kp], vhf);
                mma16816(Oacc[nd], pal[kp], vhf);
                mma16816(Oacc[nd], pah[kp], vlf);
            }
        }
    }

    // ---- epilogue: cross-half reduction, normalize, store ----
    __syncthreads();
    float* rsb = (float*)(sm + AT_RS);
    if ((lane & 3) == 0) {
        // rs identical across the 4 lanes after xor? no — reduce first
    }
    // reduce rowsums over the 4 lanes sharing a row
    rs0 += __shfl_xor_sync(0xffffffffu, rs0, 1);
    rs0 += __shfl_xor_sync(0xffffffffu, rs0, 2);
    rs1 += __shfl_xor_sync(0xffffffffu, rs1, 1);
    rs1 += __shfl_xor_sync(0xffffffffu, rs1, 2);
    if ((lane & 3) == 0) {
        rsb[wk * 128 + wq * 16 + (lane >> 2)]     = rs0;
        rsb[wk * 128 + wq * 16 + 8 + (lane >> 2)] = rs1;
    }
    if (wk == 1) {
        float* ob = (float*)(sm + AT_OBUF);
        int r0 = wq * 16 + (lane >> 2);
        #pragma unroll
        for (int nd = 0; nd < 8; nd++) {
            *(float2*)&ob[r0 * 64 + nd * 8 + (lane & 3) * 2]       = make_float2(Oacc[nd][0], Oacc[nd][1]);
            *(float2*)&ob[(r0 + 8) * 64 + nd * 8 + (lane & 3) * 2] = make_float2(Oacc[nd][2], Oacc[nd][3]);
        }
    }
    __syncthreads();
    if (wk == 0) {
        float* ob = (float*)(sm + AT_OBUF);
        int r0 = wq * 16 + (lane >> 2);
        int r1 = r0 + 8;
        float inv0 = 1.f / (rsb[r0] + rsb[128 + r0]);
        float inv1 = 1.f / (rsb[r1] + rsb[128 + r1]);
        const int b = bh >> 4, h = bh & 15;
        float* c0 = g_ctx + ((size_t)b * S_LEN + q0 + r0) * DM + h * 64 + (lane & 3) * 2;
        float* c1 = g_ctx + ((size_t)b * S_LEN + q0 + r1) * DM + h * 64 + (lane & 3) * 2;
        #pragma unroll
        for (int nd = 0; nd < 8; nd++) {
            float2 p0 = *(float2*)&ob[r0 * 64 + nd * 8 + (lane & 3) * 2];
            float2 p1 = *(float2*)&ob[r1 * 64 + nd * 8 + (lane & 3) * 2];
            *(float2*)(c0 + nd * 8) = make_float2((Oacc[nd][0] + p0.x) * inv0,
                                                  (Oacc[nd][1] + p0.y) * inv0);
            *(float2*)(c1 + nd * 8) = make_float2((Oacc[nd][2] + p1.x) * inv1,
                                                  (Oacc[nd][3] + p1.y) * inv1);
        }
        if ((lane & 3) == 0) {
            g_inv[bh * S_LEN + q0 + r0] = inv0;
            g_inv[bh * S_LEN + q0 + r1] = inv1;
        }
    }
}

// ---------------------------------------------------------------------------
// Normalize attn_weights in place (HBM-bound)
// ---------------------------------------------------------------------------
__global__ void norm_kernel(float* __restrict__ attnW)
{
    const size_t total  = (size_t)BH * S_LEN * (S_LEN / 4);
    const size_t stride = (size_t)gridDim.x * blockDim.x;
    for (size_t i = (size_t)blockIdx.x * blockDim.x + threadIdx.x; i < total; i += stride) {
        float inv = g_inv[i >> 9];
        float4 w = ((float4*)attnW)[i];
        w.x *= inv; w.y *= inv; w.z *= inv; w.w *= inv;
        ((float4*)attnW)[i] = w;
    }
}

// ---------------------------------------------------------------------------
// Launcher
// ---------------------------------------------------------------------------
#define GEMM_SMEM_BYTES 65536

extern "C" void kernel_launch(void* const* d_in, const int* in_sizes, int n_in,
                              void* d_out, int out_size)
{
    const float* x  = (const float*)d_in[0];
    const float* Wq = (const float*)d_in[1];
    const float* Wk = (const float*)d_in[2];
    const float* Wv = (const float*)d_in[3];
    const float* Wo = (const float*)d_in[4];

    float* out   = (float*)d_out;
    float* attnW = out + (size_t)MROWS * DM;

    cudaFuncSetAttribute(qkv_kernel,
                         cudaFuncAttributeMaxDynamicSharedMemorySize, GEMM_SMEM_BYTES);
    cudaFuncSetAttribute(proj_kernel,
                         cudaFuncAttributeMaxDynamicSharedMemorySize, GEMM_SMEM_BYTES);
    cudaFuncSetAttribute(attn_kernel,
                         cudaFuncAttributeMaxDynamicSharedMemorySize, AT_SMEM_BYTES);

    dim3 gq(DM / 128, MROWS / 128, 3);
    qkv_kernel<<<gq, 256, GEMM_SMEM_BYTES>>>(x, Wq, Wk, Wv);

    dim3 ga(S_LEN / 128, BH);
    attn_kernel<<<ga, 512, AT_SMEM_BYTES>>>(attnW);

    norm_kernel<<<1184, 256>>>(attnW);

    dim3 gp(DM / 128, MROWS / 128);
    proj_kernel<<<gp, 256, GEMM_SMEM_BYTES>>>(Wo, out);
}

// round 13
// speedup vs baseline: 2.3534x; 1.0400x over previous
#include <cuda_runtime.h>
#include <cuda_bf16.h>
#include <cstdint>

// Problem constants
#define S_LEN 2048
#define BATCH 2
#define HEADS 16
#define HD    64
#define DM    1024
#define BH    (BATCH*HEADS)     // 32
#define MROWS (BATCH*S_LEN)     // 4096
#define SCALE 0.125f            // 1/sqrt(64)

// ---------------------------------------------------------------------------
// Scratch: everything the GEMMs touch lives as pre-split bf16 hi/lo planes.
// ---------------------------------------------------------------------------
__device__ __nv_bfloat16 g_Qh[(size_t)BH * S_LEN * HD];
__device__ __nv_bfloat16 g_Ql[(size_t)BH * S_LEN * HD];
__device__ __nv_bfloat16 g_Kh[(size_t)BH * S_LEN * HD];
__device__ __nv_bfloat16 g_Kl[(size_t)BH * S_LEN * HD];
__device__ __nv_bfloat16 g_Vh[(size_t)BH * S_LEN * HD];
__device__ __nv_bfloat16 g_Vl[(size_t)BH * S_LEN * HD];
__device__ __nv_bfloat16 g_Xh[(size_t)MROWS * DM];
__device__ __nv_bfloat16 g_Xl[(size_t)MROWS * DM];
__device__ __nv_bfloat16 g_Wqh[(size_t)DM * DM];
__device__ __nv_bfloat16 g_Wql[(size_t)DM * DM];
__device__ __nv_bfloat16 g_Wkh[(size_t)DM * DM];
__device__ __nv_bfloat16 g_Wkl[(size_t)DM * DM];
__device__ __nv_bfloat16 g_Wvh[(size_t)DM * DM];
__device__ __nv_bfloat16 g_Wvl[(size_t)DM * DM];
__device__ __nv_bfloat16 g_Woh[(size_t)DM * DM];
__device__ __nv_bfloat16 g_Wol[(size_t)DM * DM];
__device__ __nv_bfloat16 g_Ch[(size_t)MROWS * DM];   // attention context hi
__device__ __nv_bfloat16 g_Cl[(size_t)MROWS * DM];   // attention context lo
__device__ float g_inv[BH * S_LEN];                  // 1/rowsum

// ---------------------------------------------------------------------------
// sm_80-compatible tensor-core primitives
// ---------------------------------------------------------------------------
__device__ __forceinline__ uint32_t smem_to_u32(const void* p) {
    uint32_t addr;
    asm("{ .reg .u64 tmp; cvta.to.shared.u64 tmp, %1; cvt.u32.u64 %0, tmp; }"
        : "=r"(addr) : "l"(p));
    return addr;
}
__device__ __forceinline__ void ldmx4(uint32_t (&r)[4], uint32_t addr) {
    asm volatile("ldmatrix.sync.aligned.m8n8.x4.shared.b16 {%0,%1,%2,%3}, [%4];"
        : "=r"(r[0]), "=r"(r[1]), "=r"(r[2]), "=r"(r[3]) : "r"(addr));
}
__device__ __forceinline__ void ldmx2(uint32_t (&r)[2], uint32_t addr) {
    asm volatile("ldmatrix.sync.aligned.m8n8.x2.shared.b16 {%0,%1}, [%2];"
        : "=r"(r[0]), "=r"(r[1]) : "r"(addr));
}
__device__ __forceinline__ void ldmx2t(uint32_t (&r)[2], uint32_t addr) {
    asm volatile("ldmatrix.sync.aligned.m8n8.x2.trans.shared.b16 {%0,%1}, [%2];"
        : "=r"(r[0]), "=r"(r[1]) : "r"(addr));
}
__device__ __forceinline__ void mma16816(float (&c)[4],
                                         const uint32_t (&a)[4],
                                         const uint32_t (&b)[2]) {
    asm volatile(
        "mma.sync.aligned.m16n8k16.row.col.f32.bf16.bf16.f32 "
        "{%0,%1,%2,%3}, {%4,%5,%6,%7}, {%8,%9}, {%0,%1,%2,%3};"
        : "+f"(c[0]), "+f"(c[1]), "+f"(c[2]), "+f"(c[3])
        : "r"(a[0]), "r"(a[1]), "r"(a[2]), "r"(a[3]), "r"(b[0]), "r"(b[1]));
}

#define SWZ(off) ((off) ^ (((off) >> 3) & 0x70))

// fp32 -> (hi, lo) bf16 split, packed pairwise
__device__ __forceinline__ void split2(float a, float b, uint32_t& wh, uint32_t& wl)
{
    __nv_bfloat16 ha = __float2bfloat16(a), hb = __float2bfloat16(b);
    float ra = a - __bfloat162float(ha);
    float rb = b - __bfloat162float(hb);
    __nv_bfloat16 la = __float2bfloat16(ra), lb = __float2bfloat16(rb);
    wh = (uint32_t)__bfloat16_as_ushort(ha) | ((uint32_t)__bfloat16_as_ushort(hb) << 16);
    wl = (uint32_t)__bfloat16_as_ushort(la) | ((uint32_t)__bfloat16_as_ushort(lb) << 16);
}

// ---------------------------------------------------------------------------
// Prep: split fp32 tensor into bf16 hi/lo planes. Grid-stride over pairs.
// ---------------------------------------------------------------------------
__global__ void split_kernel(const float* __restrict__ src,
                             __nv_bfloat16* __restrict__ dsth,
                             __nv_bfloat16* __restrict__ dstl, int npairs)
{
    int stride = gridDim.x * blockDim.x;
    for (int i = blockIdx.x * blockDim.x + threadIdx.x; i < npairs; i += stride) {
        float2 v = ((const float2*)src)[i];
        uint32_t hw, lw;
        split2(v.x, v.y, hw, lw);
        ((uint32_t*)dsth)[i] = hw;
        ((uint32_t*)dstl)[i] = lw;
    }
}

// ---------------------------------------------------------------------------
// HMMA GEMM mainloop over pre-split bf16 planes:
// C[128,128] tile of A[M,1024] @ B[N,1024]^T, 256 threads, warp tile 64x32,
// 3-term products (AhBh + AhBl + AlBh). No conversion work in the loop.
// ---------------------------------------------------------------------------
__device__ __forceinline__ void hmma_mainloop_bf16(
    const __nv_bfloat16* __restrict__ Ah, const __nv_bfloat16* __restrict__ Al,
    const __nv_bfloat16* __restrict__ Bh, const __nv_bfloat16* __restrict__ Bl,
    int m0, int n0, char* sm, float (&acc)[4][4][4])
{
    const int tid  = threadIdx.x;
    const int wid  = tid >> 5;
    const int lane = tid & 31;
    const int wm   = (wid & 1) * 64;
    const int wn   = (wid >> 1) * 32;
    const int lane8 = tid & 7;          // 16B sector within 128B row
    const int rgrp  = (tid >> 3) & 31;  // base row 0..31

    const uint32_t sAh = smem_to_u32(sm);
    const uint32_t sAl = sAh + 16384;
    const uint32_t sBh = sAh + 32768;
    const uint32_t sBl = sAh + 49152;

    const uint32_t a_row_lo = (lane & 15);
    const uint32_t a_kb     = (lane >> 4) * 16;
    const uint32_t b_row_lo = (lane & 7);
    const uint32_t b_kb     = ((lane >> 3) & 1) * 16;

    for (int kc = 0; kc < 16; kc++) {
        // gmem byte offsets: row stride = DM*2 bytes, chunk offset kc*128B
        const char* pAh = (const char*)(Ah + (size_t)(m0 + rgrp) * DM + kc * 64) + lane8 * 16;
        const char* pAl = (const char*)(Al + (size_t)(m0 + rgrp) * DM + kc * 64) + lane8 * 16;
        const char* pBh = (const char*)(Bh + (size_t)(n0 + rgrp) * DM + kc * 64) + lane8 * 16;
        const char* pBl = (const char*)(Bl + (size_t)(n0 + rgrp) * DM + kc * 64) + lane8 * 16;
        #pragma unroll
        for (int rr = 0; rr < 4; rr++) {
            const size_t gstep = (size_t)rr * 32 * DM * 2;
            uint32_t sw = SWZ((uint32_t)(rgrp + rr * 32) * 128 + lane8 * 16);
            *(uint4*)(sm +         sw) = *(const uint4*)(pAh + gstep);
            *(uint4*)(sm + 16384 + sw) = *(const uint4*)(pAl + gstep);
            *(uint4*)(sm + 32768 + sw) = *(const uint4*)(pBh + gstep);
            *(uint4*)(sm + 49152 + sw) = *(const uint4*)(pBl + gstep);
        }
        __syncthreads();

        #pragma unroll
        for (int ks = 0; ks < 4; ks++) {
            uint32_t ah[4][4], al[4][4];
            #pragma unroll
            for (int mi = 0; mi < 4; mi++) {
                uint32_t row = wm + mi * 16 + a_row_lo;
                uint32_t sw  = SWZ(row * 128 + ks * 32 + a_kb);
                ldmx4(ah[mi], sAh + sw);
                ldmx4(al[mi], sAl + sw);
            }
            #pragma unroll
            for (int ni = 0; ni < 4; ni++) {
                uint32_t row = wn + ni * 8 + b_row_lo;
                uint32_t sw  = SWZ(row * 128 + ks * 32 + b_kb);
                uint32_t bh[2], bl[2];
                ldmx2(bh, sBh + sw);
                ldmx2(bl, sBl + sw);
                #pragma unroll
                for (int mi = 0; mi < 4; mi++) {
                    mma16816(acc[mi][ni], ah[mi], bh);
                    mma16816(acc[mi][ni], ah[mi], bl);
                    mma16816(acc[mi][ni], al[mi], bh);
                }
            }
        }
        __syncthreads();
    }
}

// ---------------------------------------------------------------------------
// QKV projection -> pre-split bf16 hi/lo planes [bh][s][d].
// grid (8, 32, 3), 256 threads, 64KB smem.
// ---------------------------------------------------------------------------
__global__ __launch_bounds__(256, 2)
void qkv_kernel()
{
    extern __shared__ char sm[];
    const __nv_bfloat16* Wh = (blockIdx.z == 0) ? g_Wqh : (blockIdx.z == 1) ? g_Wkh : g_Wvh;
    const __nv_bfloat16* Wl = (blockIdx.z == 0) ? g_Wql : (blockIdx.z == 1) ? g_Wkl : g_Wvl;
    const int m0 = blockIdx.y * 128;
    const int n0 = blockIdx.x * 128;

    float acc[4][4][4];
    #pragma unroll
    for (int i = 0; i < 4; i++)
        #pragma unroll
        for (int j = 0; j < 4; j++)
            #pragma unroll
            for (int r = 0; r < 4; r++) acc[i][j][r] = 0.f;

    hmma_mainloop_bf16(g_Xh, g_Xl, Wh, Wl, m0, n0, sm, acc);

    const int wid  = threadIdx.x >> 5;
    const int lane = threadIdx.x & 31;
    const int wm   = (wid & 1) * 64;
    const int wn   = (wid >> 1) * 32;
    const int gr   = lane >> 2;
    const int gc   = (lane & 3) * 2;

    #pragma unroll
    for (int mi = 0; mi < 4; mi++)
        #pragma unroll
        for (int half = 0; half < 2; half++) {
            int m = m0 + wm + mi * 16 + gr + half * 8;
            int bb = m >> 11, s = m & 2047;
            #pragma unroll
            for (int ni = 0; ni < 4; ni++) {
                int n = n0 + wn + ni * 8 + gc;
                int h = n >> 6, d = n & 63;
                size_t idx = ((size_t)(bb * HEADS + h) * S_LEN + s) * HD + d;
                uint32_t hw, lw;
                split2(acc[mi][ni][half * 2], acc[mi][ni][half * 2 + 1], hw, lw);
                if (blockIdx.z == 0) {
                    *(uint32_t*)(g_Qh + idx) = hw;
                    *(uint32_t*)(g_Ql + idx) = lw;
                } else if (blockIdx.z == 1) {
                    *(uint32_t*)(g_Kh + idx) = hw;
                    *(uint32_t*)(g_Kl + idx) = lw;
                } else {
                    *(uint32_t*)(g_Vh + idx) = hw;
                    *(uint32_t*)(g_Vl + idx) = lw;
                }
            }
        }
}

// ---------------------------------------------------------------------------
// Output projection: out = ctx @ Wo^T. grid (8, 32), 256 threads.
// ---------------------------------------------------------------------------
__global__ __launch_bounds__(256, 2)
void proj_kernel(float* __restrict__ Out)
{
    extern __shared__ char sm[];
    const int m0 = blockIdx.y * 128;
    const int n0 = blockIdx.x * 128;

    float acc[4][4][4];
    #pragma unroll
    for (int i = 0; i < 4; i++)
        #pragma unroll
        for (int j = 0; j < 4; j++)
            #pragma unroll
            for (int r = 0; r < 4; r++) acc[i][j][r] = 0.f;

    hmma_mainloop_bf16(g_Ch, g_Cl, g_Woh, g_Wol, m0, n0, sm, acc);

    const int wid  = threadIdx.x >> 5;
    const int lane = threadIdx.x & 31;
    const int wm   = (wid & 1) * 64;
    const int wn   = (wid >> 1) * 32;
    const int gr   = lane >> 2;
    const int gc   = (lane & 3) * 2;

    #pragma unroll
    for (int mi = 0; mi < 4; mi++)
        #pragma unroll
        for (int half = 0; half < 2; half++) {
            int m = m0 + wm + mi * 16 + gr + half * 8;
            float* row = Out + (size_t)m * DM + n0 + wn + gc;
            #pragma unroll
            for (int ni = 0; ni < 4; ni++)
                *(float2*)(row + ni * 8) = make_float2(acc[mi][ni][half * 2],
                                                       acc[mi][ni][half * 2 + 1]);
        }
}

// ---------------------------------------------------------------------------
// HMMA attention (from passing round 8; ctx now written as bf16 hi/lo planes).
// CTA = 128 queries x one (b,h). 512 threads = 16 warps: warp tile 16q x 64k,
// key dim split over 2 warp groups.
// ---------------------------------------------------------------------------
#define AT_QH   0
#define AT_QL   16384
#define AT_KH   32768
#define AT_KL   49152
#define AT_VH   65536
#define AT_VL   81920
#define AT_OBUF 65536           /* reuse V region after mainloop: f32[128][64] */
#define AT_RS   98304           /* f32[2][128] */
#define AT_SMEM_BYTES (98304 + 1024)

__global__ __launch_bounds__(512, 1)
void attn_kernel(float* __restrict__ attnW)
{
    extern __shared__ char sm[];
    const int tid  = threadIdx.x;
    const int wid  = tid >> 5;
    const int lane = tid & 31;
    const int wq   = wid & 7;       // q block (16 rows)
    const int wk   = wid >> 3;      // key half (64 cols)
    const int bh   = blockIdx.y;
    const int q0   = blockIdx.x * 128;

    const size_t plane = (size_t)bh * S_LEN * HD;

    // ---- load Q tile (once) ----
    {
        const __nv_bfloat16* qh = g_Qh + plane + (size_t)q0 * HD;
        const __nv_bfloat16* ql = g_Ql + plane + (size_t)q0 * HD;
        #pragma unroll
        for (int it = 0; it < 2; it++) {
            int i = tid + it * 512;
            int row = i >> 3, c16 = i & 7;
            uint32_t sw = SWZ((uint32_t)(row * 128 + c16 * 16));
            *(uint4*)(sm + AT_QH + sw) = *(const uint4*)((const char*)(qh + (size_t)row * 64) + c16 * 16);
            *(uint4*)(sm + AT_QL + sw) = *(const uint4*)((const char*)(ql + (size_t)row * 64) + c16 * 16);
        }
    }

    const uint32_t sbase = smem_to_u32(sm);
    const uint32_t a_off = (uint32_t)((wq * 16 + (lane & 15)) * 128 + (lane >> 4) * 16);
    const uint32_t b_row = (uint32_t)(wk * 64 + (lane & 7));
    const uint32_t b_kb  = ((lane >> 3) & 1) * 16;
    const uint32_t v_row = (uint32_t)(wk * 64 + (lane & 15));

    float Oacc[8][4];
    #pragma unroll
    for (int i = 0; i < 8; i++)
        #pragma unroll
        for (int j = 0; j < 4; j++) Oacc[i][j] = 0.f;
    float rs0 = 0.f, rs1 = 0.f;

    for (int kt = 0; kt < 16; kt++) {
        const int k0 = kt * 128;
        __syncthreads();
        {
            const __nv_bfloat16* kh = g_Kh + plane + (size_t)k0 * HD;
            const __nv_bfloat16* kl = g_Kl + plane + (size_t)k0 * HD;
            const __nv_bfloat16* vh = g_Vh + plane + (size_t)k0 * HD;
            const __nv_bfloat16* vl = g_Vl + plane + (size_t)k0 * HD;
            #pragma unroll
            for (int it = 0; it < 2; it++) {
                int i = tid + it * 512;
                int row = i >> 3, c16 = i & 7;
                uint32_t sw = SWZ((uint32_t)(row * 128 + c16 * 16));
                size_t gb = (size_t)row * 64;
                *(uint4*)(sm + AT_KH + sw) = *(const uint4*)((const char*)(kh + gb) + c16 * 16);
                *(uint4*)(sm + AT_KL + sw) = *(const uint4*)((const char*)(kl + gb) + c16 * 16);
                *(uint4*)(sm + AT_VH + sw) = *(const uint4*)((const char*)(vh + gb) + c16 * 16);
                *(uint4*)(sm + AT_VL + sw) = *(const uint4*)((const char*)(vl + gb) + c16 * 16);
            }
        }
        __syncthreads();

        // ---- S = Q K^T (warp: 16q x 64k), 3-MMA split ----
        float Sacc[8][4];
        #pragma unroll
        for (int i = 0; i < 8; i++)
            #pragma unroll
            for (int j = 0; j < 4; j++) Sacc[i][j] = 0.f;

        #pragma unroll
        for (int ks = 0; ks < 4; ks++) {
            uint32_t ah[4], al[4];
            uint32_t qa = SWZ(a_off + ks * 32);
            ldmx4(ah, sbase + AT_QH + qa);
            ldmx4(al, sbase + AT_QL + qa);
            #pragma unroll
            for (int ni = 0; ni < 8; ni++) {
                uint32_t ka = SWZ((b_row + ni * 8) * 128 + ks * 32 + b_kb);
                uint32_t kf[2], klf[2];
                ldmx2(kf,  sbase + AT_KH + ka);
                ldmx2(klf, sbase + AT_KL + ka);
                mma16816(Sacc[ni], ah, kf);
                mma16816(Sacc[ni], ah, klf);
                mma16816(Sacc[ni], al, kf);
            }
        }

        // ---- exp + attnW store + rowsum + repack to A-fragments ----
        uint32_t pah[4][4], pal[4][4];
        float* Wrow = attnW + ((size_t)bh * S_LEN + q0 + wq * 16 + (lane >> 2)) * S_LEN
                    + k0 + wk * 64 + (lane & 3) * 2;
        #pragma unroll
        for (int ni = 0; ni < 8; ni++) {
            float e0 = __expf(Sacc[ni][0] * SCALE);
            float e1 = __expf(Sacc[ni][1] * SCALE);
            float e2 = __expf(Sacc[ni][2] * SCALE);
            float e3 = __expf(Sacc[ni][3] * SCALE);
            rs0 += e0 + e1;
            rs1 += e2 + e3;
            *(float2*)(Wrow + ni * 8)                      = make_float2(e0, e1);
            *(float2*)(Wrow + (size_t)8 * S_LEN + ni * 8)  = make_float2(e2, e3);
            uint32_t h01, l01, h23, l23;
            split2(e0, e1, h01, l01);
            split2(e2, e3, h23, l23);
            int kp = ni >> 1, o = (ni & 1) * 2;
            pah[kp][o] = h01; pah[kp][o + 1] = h23;
            pal[kp][o] = l01; pal[kp][o + 1] = l23;
        }

        // ---- O += P @ V (warp: 16q x 64d over its 64-key half) ----
        #pragma unroll
        for (int kp = 0; kp < 4; kp++) {
            #pragma unroll
            for (int nd = 0; nd < 8; nd++) {
                uint32_t va = SWZ((v_row + kp * 16) * 128 + nd * 16);
                uint32_t vhf[2], vlf[2];
                ldmx2t(vhf, sbase + AT_VH + va);
                ldmx2t(vlf, sbase + AT_VL + va);
                mma16816(Oacc[nd], pah[kp], vhf);
                mma16816(Oacc[nd], pal[kp], vhf);
                mma16816(Oacc[nd], pah[kp], vlf);
            }
        }
    }

    // ---- epilogue: cross-half reduction, normalize, store split ctx ----
    __syncthreads();
    float* rsb = (float*)(sm + AT_RS);
    rs0 += __shfl_xor_sync(0xffffffffu, rs0, 1);
    rs0 += __shfl_xor_sync(0xffffffffu, rs0, 2);
    rs1 += __shfl_xor_sync(0xffffffffu, rs1, 1);
    rs1 += __shfl_xor_sync(0xffffffffu, rs1, 2);
    if ((lane & 3) == 0) {
        rsb[wk * 128 + wq * 16 + (lane >> 2)]     = rs0;
        rsb[wk * 128 + wq * 16 + 8 + (lane >> 2)] = rs1;
    }
    if (wk == 1) {
        float* ob = (float*)(sm + AT_OBUF);
        int r0 = wq * 16 + (lane >> 2);
        #pragma unroll
        for (int nd = 0; nd < 8; nd++) {
            *(float2*)&ob[r0 * 64 + nd * 8 + (lane & 3) * 2]       = make_float2(Oacc[nd][0], Oacc[nd][1]);
            *(float2*)&ob[(r0 + 8) * 64 + nd * 8 + (lane & 3) * 2] = make_float2(Oacc[nd][2], Oacc[nd][3]);
        }
    }
    __syncthreads();
    if (wk == 0) {
        float* ob = (float*)(sm + AT_OBUF);
        int r0 = wq * 16 + (lane >> 2);
        int r1 = r0 + 8;
        float inv0 = 1.f / (rsb[r0] + rsb[128 + r0]);
        float inv1 = 1.f / (rsb[r1] + rsb[128 + r1]);
        const int b = bh >> 4, h = bh & 15;
        size_t i0 = ((size_t)b * S_LEN + q0 + r0) * DM + h * 64 + (lane & 3) * 2;
        size_t i1 = ((size_t)b * S_LEN + q0 + r1) * DM + h * 64 + (lane & 3) * 2;
        #pragma unroll
        for (int nd = 0; nd < 8; nd++) {
            float2 p0 = *(float2*)&ob[r0 * 64 + nd * 8 + (lane & 3) * 2];
            float2 p1 = *(float2*)&ob[r1 * 64 + nd * 8 + (lane & 3) * 2];
            uint32_t hw, lw;
            split2((Oacc[nd][0] + p0.x) * inv0, (Oacc[nd][1] + p0.y) * inv0, hw, lw);
            *(uint32_t*)(g_Ch + i0 + nd * 8) = hw;
            *(uint32_t*)(g_Cl + i0 + nd * 8) = lw;
            split2((Oacc[nd][2] + p1.x) * inv1, (Oacc[nd][3] + p1.y) * inv1, hw, lw);
            *(uint32_t*)(g_Ch + i1 + nd * 8) = hw;
            *(uint32_t*)(g_Cl + i1 + nd * 8) = lw;
        }
        if ((lane & 3) == 0) {
            g_inv[bh * S_LEN + q0 + r0] = inv0;
            g_inv[bh * S_LEN + q0 + r1] = inv1;
        }
    }
}

// ---------------------------------------------------------------------------
// Normalize attn_weights in place (HBM-bound)
// ---------------------------------------------------------------------------
__global__ void norm_kernel(float* __restrict__ attnW)
{
    const size_t total  = (size_t)BH * S_LEN * (S_LEN / 4);
    const size_t stride = (size_t)gridDim.x * blockDim.x;
    for (size_t i = (size_t)blockIdx.x * blockDim.x + threadIdx.x; i < total; i += stride) {
        float inv = g_inv[i >> 9];
        float4 w = ((float4*)attnW)[i];
        w.x *= inv; w.y *= inv; w.z *= inv; w.w *= inv;
        ((float4*)attnW)[i] = w;
    }
}

// ---------------------------------------------------------------------------
// Launcher
// ---------------------------------------------------------------------------
#define GEMM_SMEM_BYTES 65536

extern "C" void kernel_launch(void* const* d_in, const int* in_sizes, int n_in,
                              void* d_out, int out_size)
{
    const float* x  = (const float*)d_in[0];
    const float* Wq = (const float*)d_in[1];
    const float* Wk = (const float*)d_in[2];
    const float* Wv = (const float*)d_in[3];
    const float* Wo = (const float*)d_in[4];

    float* out   = (float*)d_out;
    float* attnW = out + (size_t)MROWS * DM;

    cudaFuncSetAttribute(qkv_kernel,
                         cudaFuncAttributeMaxDynamicSharedMemorySize, GEMM_SMEM_BYTES);
    cudaFuncSetAttribute(proj_kernel,
                         cudaFuncAttributeMaxDynamicSharedMemorySize, GEMM_SMEM_BYTES);
    cudaFuncSetAttribute(attn_kernel,
                         cudaFuncAttributeMaxDynamicSharedMemorySize, AT_SMEM_BYTES);

    __nv_bfloat16 *Xh, *Xl, *Wqh, *Wql, *Wkh, *Wkl, *Wvh, *Wvl, *Woh, *Wol;
    cudaGetSymbolAddress((void**)&Xh,  g_Xh);  cudaGetSymbolAddress((void**)&Xl,  g_Xl);
    cudaGetSymbolAddress((void**)&Wqh, g_Wqh); cudaGetSymbolAddress((void**)&Wql, g_Wql);
    cudaGetSymbolAddress((void**)&Wkh, g_Wkh); cudaGetSymbolAddress((void**)&Wkl, g_Wkl);
    cudaGetSymbolAddress((void**)&Wvh, g_Wvh); cudaGetSymbolAddress((void**)&Wvl, g_Wvl);
    cudaGetSymbolAddress((void**)&Woh, g_Woh); cudaGetSymbolAddress((void**)&Wol, g_Wol);

    split_kernel<<<2048, 256>>>(x,  Xh,  Xl,  MROWS * DM / 2);
    split_kernel<<<1024, 256>>>(Wq, Wqh, Wql, DM * DM / 2);
    split_kernel<<<1024, 256>>>(Wk, Wkh, Wkl, DM * DM / 2);
    split_kernel<<<1024, 256>>>(Wv, Wvh, Wvl, DM * DM / 2);
    split_kernel<<<1024, 256>>>(Wo, Woh, Wol, DM * DM / 2);

    dim3 gq(DM / 128, MROWS / 128, 3);
    qkv_kernel<<<gq, 256, GEMM_SMEM_BYTES>>>();

    dim3 ga(S_LEN / 128, BH);
    attn_kernel<<<ga, 512, AT_SMEM_BYTES>>>(attnW);

    norm_kernel<<<1184, 256>>>(attnW);

    dim3 gp(DM / 128, MROWS / 128);
    proj_kernel<<<gp, 256, GEMM_SMEM_BYTES>>>(out);
}

// round 15
// speedup vs baseline: 2.5276x; 1.0740x over previous
#include <cuda_runtime.h>
#include <cuda_bf16.h>
#include <cstdint>

// Problem constants
#define S_LEN 2048
#define BATCH 2
#define HEADS 16
#define HD    64
#define DM    1024
#define BH    (BATCH*HEADS)     // 32
#define MROWS (BATCH*S_LEN)     // 4096
#define SCALE 0.125f            // 1/sqrt(64)

// ---------------------------------------------------------------------------
// Scratch: everything the GEMMs touch lives as pre-split bf16 hi/lo planes.
// ---------------------------------------------------------------------------
__device__ __nv_bfloat16 g_Qh[(size_t)BH * S_LEN * HD];
__device__ __nv_bfloat16 g_Ql[(size_t)BH * S_LEN * HD];
__device__ __nv_bfloat16 g_Kh[(size_t)BH * S_LEN * HD];
__device__ __nv_bfloat16 g_Kl[(size_t)BH * S_LEN * HD];
__device__ __nv_bfloat16 g_Vh[(size_t)BH * S_LEN * HD];
__device__ __nv_bfloat16 g_Vl[(size_t)BH * S_LEN * HD];
__device__ __nv_bfloat16 g_Xh[(size_t)MROWS * DM];
__device__ __nv_bfloat16 g_Xl[(size_t)MROWS * DM];
__device__ __nv_bfloat16 g_Wqh[(size_t)DM * DM];
__device__ __nv_bfloat16 g_Wql[(size_t)DM * DM];
__device__ __nv_bfloat16 g_Wkh[(size_t)DM * DM];
__device__ __nv_bfloat16 g_Wkl[(size_t)DM * DM];
__device__ __nv_bfloat16 g_Wvh[(size_t)DM * DM];
__device__ __nv_bfloat16 g_Wvl[(size_t)DM * DM];
__device__ __nv_bfloat16 g_Woh[(size_t)DM * DM];
__device__ __nv_bfloat16 g_Wol[(size_t)DM * DM];
__device__ __nv_bfloat16 g_Ch[(size_t)MROWS * DM];   // attention context hi
__device__ __nv_bfloat16 g_Cl[(size_t)MROWS * DM];   // attention context lo
__device__ float g_inv[BH * S_LEN];                  // 1/rowsum

// ---------------------------------------------------------------------------
// sm_80-compatible primitives
// ---------------------------------------------------------------------------
__device__ __forceinline__ uint32_t smem_to_u32(const void* p) {
    uint32_t addr;
    asm("{ .reg .u64 tmp; cvta.to.shared.u64 tmp, %1; cvt.u32.u64 %0, tmp; }"
        : "=r"(addr) : "l"(p));
    return addr;
}
__device__ __forceinline__ void ldmx4(uint32_t (&r)[4], uint32_t addr) {
    asm volatile("ldmatrix.sync.aligned.m8n8.x4.shared.b16 {%0,%1,%2,%3}, [%4];"
        : "=r"(r[0]), "=r"(r[1]), "=r"(r[2]), "=r"(r[3]) : "r"(addr));
}
__device__ __forceinline__ void ldmx2(uint32_t (&r)[2], uint32_t addr) {
    asm volatile("ldmatrix.sync.aligned.m8n8.x2.shared.b16 {%0,%1}, [%2];"
        : "=r"(r[0]), "=r"(r[1]) : "r"(addr));
}
__device__ __forceinline__ void ldmx2t(uint32_t (&r)[2], uint32_t addr) {
    asm volatile("ldmatrix.sync.aligned.m8n8.x2.trans.shared.b16 {%0,%1}, [%2];"
        : "=r"(r[0]), "=r"(r[1]) : "r"(addr));
}
__device__ __forceinline__ void mma16816(float (&c)[4],
                                         const uint32_t (&a)[4],
                                         const uint32_t (&b)[2]) {
    asm volatile(
        "mma.sync.aligned.m16n8k16.row.col.f32.bf16.bf16.f32 "
        "{%0,%1,%2,%3}, {%4,%5,%6,%7}, {%8,%9}, {%0,%1,%2,%3};"
        : "+f"(c[0]), "+f"(c[1]), "+f"(c[2]), "+f"(c[3])
        : "r"(a[0]), "r"(a[1]), "r"(a[2]), "r"(a[3]), "r"(b[0]), "r"(b[1]));
}

#define CP16(dst, src) \
    asm volatile("cp.async.cg.shared.global [%0], [%1], 16;" \
        :: "r"((uint32_t)(dst)), "l"((const void*)(src)))
#define CP_COMMIT() asm volatile("cp.async.commit_group;" ::: "memory")
#define CP_WAIT1()  asm volatile("cp.async.wait_group 1;" ::: "memory")
#define CP_WAIT0()  asm volatile("cp.async.wait_group 0;" ::: "memory")

#define SWZ(off) ((off) ^ (((off) >> 3) & 0x70))

// fp32 -> (hi, lo) bf16 split, packed pairwise
__device__ __forceinline__ void split2(float a, float b, uint32_t& wh, uint32_t& wl)
{
    __nv_bfloat16 ha = __float2bfloat16(a), hb = __float2bfloat16(b);
    float ra = a - __bfloat162float(ha);
    float rb = b - __bfloat162float(hb);
    __nv_bfloat16 la = __float2bfloat16(ra), lb = __float2bfloat16(rb);
    wh = (uint32_t)__bfloat16_as_ushort(ha) | ((uint32_t)__bfloat16_as_ushort(hb) << 16);
    wl = (uint32_t)__bfloat16_as_ushort(la) | ((uint32_t)__bfloat16_as_ushort(lb) << 16);
}

// ---------------------------------------------------------------------------
// Prep: split fp32 tensor into bf16 hi/lo planes. Grid-stride over pairs.
// ---------------------------------------------------------------------------
__global__ void split_kernel(const float* __restrict__ src,
                             __nv_bfloat16* __restrict__ dsth,
                             __nv_bfloat16* __restrict__ dstl, int npairs)
{
    int stride = gridDim.x * blockDim.x;
    for (int i = blockIdx.x * blockDim.x + threadIdx.x; i < npairs; i += stride) {
        float2 v = ((const float2*)src)[i];
        uint32_t hw, lw;
        split2(v.x, v.y, hw, lw);
        ((uint32_t*)dsth)[i] = hw;
        ((uint32_t*)dstl)[i] = lw;
    }
}

// ---------------------------------------------------------------------------
// HMMA GEMM mainloop, cp.async double-buffered. 2 stages x 64KB.
// C[128,128] tile of A[M,1024] @ B[N,1024]^T, 256 threads, warp tile 64x32,
// 3-term products (AhBh + AhBl + AlBh).
// Stage layout (stride 65536): Ah +0, Al +16384, Bh +32768, Bl +49152.
// ---------------------------------------------------------------------------
__device__ __forceinline__ void hmma_mainloop_bf16(
    const __nv_bfloat16* __restrict__ Ah, const __nv_bfloat16* __restrict__ Al,
    const __nv_bfloat16* __restrict__ Bh, const __nv_bfloat16* __restrict__ Bl,
    int m0, int n0, char* sm, float (&acc)[4][4][4])
{
    const int tid  = threadIdx.x;
    const int wid  = tid >> 5;
    const int lane = tid & 31;
    const int wm   = (wid & 1) * 64;
    const int wn   = (wid >> 1) * 32;
    const int lane8 = tid & 7;          // 16B sector within 128B row
    const int rgrp  = (tid >> 3) & 31;  // base row 0..31

    const uint32_t sbase = smem_to_u32(sm);
    const uint32_t a_row_lo = (lane & 15);
    const uint32_t a_kb     = (lane >> 4) * 16;
    const uint32_t b_row_lo = (lane & 7);
    const uint32_t b_kb     = ((lane >> 3) & 1) * 16;

    // precompute swizzled store offsets (4 rows per thread)
    uint32_t ssw[4];
    #pragma unroll
    for (int rr = 0; rr < 4; rr++)
        ssw[rr] = SWZ((uint32_t)(rgrp + rr * 32) * 128 + lane8 * 16);

    // ---- prologue: issue chunk 0 into stage 0 ----
    {
        const char* pAh = (const char*)(Ah + (size_t)(m0 + rgrp) * DM) + lane8 * 16;
        const char* pAl = (const char*)(Al + (size_t)(m0 + rgrp) * DM) + lane8 * 16;
        const char* pBh = (const char*)(Bh + (size_t)(n0 + rgrp) * DM) + lane8 * 16;
        const char* pBl = (const char*)(Bl + (size_t)(n0 + rgrp) * DM) + lane8 * 16;
        #pragma unroll
        for (int rr = 0; rr < 4; rr++) {
            const size_t g = (size_t)rr * 32 * DM * 2;
            CP16(sbase +         ssw[rr], pAh + g);
            CP16(sbase + 16384 + ssw[rr], pAl + g);
            CP16(sbase + 32768 + ssw[rr], pBh + g);
            CP16(sbase + 49152 + ssw[rr], pBl + g);
        }
        CP_COMMIT();
    }

    for (int kc = 0; kc < 16; kc++) {
        if (kc < 15) {
            const uint32_t sb = sbase + ((kc + 1) & 1) * 65536;
            const size_t goff = (size_t)(kc + 1) * 128;  // bytes into row
            const char* pAh = (const char*)(Ah + (size_t)(m0 + rgrp) * DM) + goff + lane8 * 16;
            const char* pAl = (const char*)(Al + (size_t)(m0 + rgrp) * DM) + goff + lane8 * 16;
            const char* pBh = (const char*)(Bh + (size_t)(n0 + rgrp) * DM) + goff + lane8 * 16;
            const char* pBl = (const char*)(Bl + (size_t)(n0 + rgrp) * DM) + goff + lane8 * 16;
            #pragma unroll
            for (int rr = 0; rr < 4; rr++) {
                const size_t g = (size_t)rr * 32 * DM * 2;
                CP16(sb +         ssw[rr], pAh + g);
                CP16(sb + 16384 + ssw[rr], pAl + g);
                CP16(sb + 32768 + ssw[rr], pBh + g);
                CP16(sb + 49152 + ssw[rr], pBl + g);
            }
            CP_COMMIT();
            CP_WAIT1();
        } else {
            CP_WAIT0();
        }
        __syncthreads();

        const uint32_t sb = sbase + (kc & 1) * 65536;
        #pragma unroll
        for (int ks = 0; ks < 4; ks++) {
            uint32_t ah[4][4], al[4][4];
            #pragma unroll
            for (int mi = 0; mi < 4; mi++) {
                uint32_t row = wm + mi * 16 + a_row_lo;
                uint32_t sw  = SWZ(row * 128 + ks * 32 + a_kb);
                ldmx4(ah[mi], sb + sw);
                ldmx4(al[mi], sb + 16384 + sw);
            }
            #pragma unroll
            for (int ni = 0; ni < 4; ni++) {
                uint32_t row = wn + ni * 8 + b_row_lo;
                uint32_t sw  = SWZ(row * 128 + ks * 32 + b_kb);
                uint32_t bh[2], bl[2];
                ldmx2(bh, sb + 32768 + sw);
                ldmx2(bl, sb + 49152 + sw);
                #pragma unroll
                for (int mi = 0; mi < 4; mi++) {
                    mma16816(acc[mi][ni], ah[mi], bh);
                    mma16816(acc[mi][ni], ah[mi], bl);
                    mma16816(acc[mi][ni], al[mi], bh);
                }
            }
        }
        __syncthreads();
    }
}

// ---------------------------------------------------------------------------
// QKV projection -> pre-split bf16 hi/lo planes [bh][s][d].
// grid (8, 32, 3), 256 threads, 128KB smem.
// ---------------------------------------------------------------------------
__global__ __launch_bounds__(256, 1)
void qkv_kernel()
{
    extern __shared__ char sm[];
    const __nv_bfloat16* Wh = (blockIdx.z == 0) ? g_Wqh : (blockIdx.z == 1) ? g_Wkh : g_Wvh;
    const __nv_bfloat16* Wl = (blockIdx.z == 0) ? g_Wql : (blockIdx.z == 1) ? g_Wkl : g_Wvl;
    const int m0 = blockIdx.y * 128;
    const int n0 = blockIdx.x * 128;

    float acc[4][4][4];
    #pragma unroll
    for (int i = 0; i < 4; i++)
        #pragma unroll
        for (int j = 0; j < 4; j++)
            #pragma unroll
            for (int r = 0; r < 4; r++) acc[i][j][r] = 0.f;

    hmma_mainloop_bf16(g_Xh, g_Xl, Wh, Wl, m0, n0, sm, acc);

    const int wid  = threadIdx.x >> 5;
    const int lane = threadIdx.x & 31;
    const int wm   = (wid & 1) * 64;
    const int wn   = (wid >> 1) * 32;
    const int gr   = lane >> 2;
    const int gc   = (lane & 3) * 2;

    #pragma unroll
    for (int mi = 0; mi < 4; mi++)
        #pragma unroll
        for (int half = 0; half < 2; half++) {
            int m = m0 + wm + mi * 16 + gr + half * 8;
            int bb = m >> 11, s = m & 2047;
            #pragma unroll
            for (int ni = 0; ni < 4; ni++) {
                int n = n0 + wn + ni * 8 + gc;
                int h = n >> 6, d = n & 63;
                size_t idx = ((size_t)(bb * HEADS + h) * S_LEN + s) * HD + d;
                uint32_t hw, lw;
                split2(acc[mi][ni][half * 2], acc[mi][ni][half * 2 + 1], hw, lw);
                if (blockIdx.z == 0) {
                    *(uint32_t*)(g_Qh + idx) = hw;
                    *(uint32_t*)(g_Ql + idx) = lw;
                } else if (blockIdx.z == 1) {
                    *(uint32_t*)(g_Kh + idx) = hw;
                    *(uint32_t*)(g_Kl + idx) = lw;
                } else {
                    *(uint32_t*)(g_Vh + idx) = hw;
                    *(uint32_t*)(g_Vl + idx) = lw;
                }
            }
        }
}

// ---------------------------------------------------------------------------
// Output projection: out = ctx @ Wo^T. grid (8, 32), 256 threads.
// ---------------------------------------------------------------------------
__global__ __launch_bounds__(256, 1)
void proj_kernel(float* __restrict__ Out)
{
    extern __shared__ char sm[];
    const int m0 = blockIdx.y * 128;
    const int n0 = blockIdx.x * 128;

    float acc[4][4][4];
    #pragma unroll
    for (int i = 0; i < 4; i++)
        #pragma unroll
        for (int j = 0; j < 4; j++)
            #pragma unroll
            for (int r = 0; r < 4; r++) acc[i][j][r] = 0.f;

    hmma_mainloop_bf16(g_Ch, g_Cl, g_Woh, g_Wol, m0, n0, sm, acc);

    const int wid  = threadIdx.x >> 5;
    const int lane = threadIdx.x & 31;
    const int wm   = (wid & 1) * 64;
    const int wn   = (wid >> 1) * 32;
    const int gr   = lane >> 2;
    const int gc   = (lane & 3) * 2;

    #pragma unroll
    for (int mi = 0; mi < 4; mi++)
        #pragma unroll
        for (int half = 0; half < 2; half++) {
            int m = m0 + wm + mi * 16 + gr + half * 8;
            float* row = Out + (size_t)m * DM + n0 + wn + gc;
            #pragma unroll
            for (int ni = 0; ni < 4; ni++)
                *(float2*)(row + ni * 8) = make_float2(acc[mi][ni][half * 2],
                                                       acc[mi][ni][half * 2 + 1]);
        }
}

// ---------------------------------------------------------------------------
// HMMA attention, cp.async double-buffered K/V.
// CTA = 128 queries x one (b,h). 512 threads = 16 warps: warp tile 16q x 64k,
// key dim split over 2 warp groups.
// smem: Q hi/lo 32KB resident; 2 KV stages of 64KB (KH,KL,VH,VL @16KB).
// OBUF/RS reuse stage 0 after the mainloop.
// ---------------------------------------------------------------------------
#define AT_STAGE0 32768
#define AT_OBUF   32768                 /* f32[128][64] = 32KB (stage0 KH/KL) */
#define AT_RS     65536                 /* f32[2][128]  (stage0 VH)           */
#define AT_SMEM_BYTES (32768 + 2 * 65536)

__global__ __launch_bounds__(512, 1)
void attn_kernel(float* __restrict__ attnW)
{
    extern __shared__ char sm[];
    const int tid  = threadIdx.x;
    const int wid  = tid >> 5;
    const int lane = tid & 31;
    const int wq   = wid & 7;       // q block (16 rows)
    const int wk   = wid >> 3;      // key half (64 cols)
    const int bh   = blockIdx.y;
    const int q0   = blockIdx.x * 128;

    const size_t plane = (size_t)bh * S_LEN * HD;
    const uint32_t sbase = smem_to_u32(sm);

    // per-thread load geometry (2 x 16B per plane per tile)
    const int l_row0 = tid >> 3;            // rows 0..63
    const int l_c16  = tid & 7;
    const uint32_t lsw0 = SWZ((uint32_t)(l_row0 * 128 + l_c16 * 16));
    const uint32_t lsw1 = SWZ((uint32_t)((l_row0 + 64) * 128 + l_c16 * 16));
    const size_t gb0 = (size_t)l_row0 * 64;
    const size_t gb1 = (size_t)(l_row0 + 64) * 64;

    // ---- load Q tile (plain, covered by first barrier) ----
    {
        const __nv_bfloat16* qh = g_Qh + plane + (size_t)q0 * HD;
        const __nv_bfloat16* ql = g_Ql + plane + (size_t)q0 * HD;
        *(uint4*)(sm + lsw0)         = *(const uint4*)((const char*)(qh + gb0) + l_c16 * 16);
        *(uint4*)(sm + lsw1)         = *(const uint4*)((const char*)(qh + gb1) + l_c16 * 16);
        *(uint4*)(sm + 16384 + lsw0) = *(const uint4*)((const char*)(ql + gb0) + l_c16 * 16);
        *(uint4*)(sm + 16384 + lsw1) = *(const uint4*)((const char*)(ql + gb1) + l_c16 * 16);
    }

    // ---- prologue: issue K/V tile 0 into stage 0 ----
    {
        const __nv_bfloat16* kh = g_Kh + plane;
        const __nv_bfloat16* kl = g_Kl + plane;
        const __nv_bfloat16* vh = g_Vh + plane;
        const __nv_bfloat16* vl = g_Vl + plane;
        const uint32_t sb = sbase + AT_STAGE0;
        CP16(sb +         lsw0, (const char*)(kh + gb0) + l_c16 * 16);
        CP16(sb +         lsw1, (const char*)(kh + gb1) + l_c16 * 16);
        CP16(sb + 16384 + lsw0, (const char*)(kl + gb0) + l_c16 * 16);
        CP16(sb + 16384 + lsw1, (const char*)(kl + gb1) + l_c16 * 16);
        CP16(sb + 32768 + lsw0, (const char*)(vh + gb0) + l_c16 * 16);
        CP16(sb + 32768 + lsw1, (const char*)(vh + gb1) + l_c16 * 16);
        CP16(sb + 49152 + lsw0, (const char*)(vl + gb0) + l_c16 * 16);
        CP16(sb + 49152 + lsw1, (const char*)(vl + gb1) + l_c16 * 16);
        CP_COMMIT();
    }

    const uint32_t a_off = (uint32_t)((wq * 16 + (lane & 15)) * 128 + (lane >> 4) * 16);
    const uint32_t b_row = (uint32_t)(wk * 64 + (lane & 7));
    const uint32_t b_kb  = ((lane >> 3) & 1) * 16;
    const uint32_t v_row = (uint32_t)(wk * 64 + (lane & 15));

    float Oacc[8][4];
    #pragma unroll
    for (int i = 0; i < 8; i++)
        #pragma unroll
        for (int j = 0; j < 4; j++) Oacc[i][j] = 0.f;
    float rs0 = 0.f, rs1 = 0.f;

    for (int kt = 0; kt < 16; kt++) {
        if (kt < 15) {
            const int k1 = (kt + 1) * 128;
            const __nv_bfloat16* kh = g_Kh + plane + (size_t)k1 * HD;
            const __nv_bfloat16* kl = g_Kl + plane + (size_t)k1 * HD;
            const __nv_bfloat16* vh = g_Vh + plane + (size_t)k1 * HD;
            const __nv_bfloat16* vl = g_Vl + plane + (size_t)k1 * HD;
            const uint32_t sb = sbase + AT_STAGE0 + ((kt + 1) & 1) * 65536;
            CP16(sb +         lsw0, (const char*)(kh + gb0) + l_c16 * 16);
            CP16(sb +         lsw1, (const char*)(kh + gb1) + l_c16 * 16);
            CP16(sb + 16384 + lsw0, (const char*)(kl + gb0) + l_c16 * 16);
            CP16(sb + 16384 + lsw1, (const char*)(kl + gb1) + l_c16 * 16);
            CP16(sb + 32768 + lsw0, (const char*)(vh + gb0) + l_c16 * 16);
            CP16(sb + 32768 + lsw1, (const char*)(vh + gb1) + l_c16 * 16);
            CP16(sb + 49152 + lsw0, (const char*)(vl + gb0) + l_c16 * 16);
            CP16(sb + 49152 + lsw1, (const char*)(vl + gb1) + l_c16 * 16);
            CP_COMMIT();
            CP_WAIT1();
        } else {
            CP_WAIT0();
        }
        __syncthreads();

        const int k0 = kt * 128;
        const uint32_t kvb = AT_STAGE0 + (kt & 1) * 65536;

        // ---- S = Q K^T (warp: 16q x 64k), 3-MMA split ----
        float Sacc[8][4];
        #pragma unroll
        for (int i = 0; i < 8; i++)
            #pragma unroll
            for (int j = 0; j < 4; j++) Sacc[i][j] = 0.f;

        #pragma unroll
        for (int ks = 0; ks < 4; ks++) {
            uint32_t ah[4], al[4];
            uint32_t qa = SWZ(a_off + ks * 32);
            ldmx4(ah, sbase + qa);
            ldmx4(al, sbase + 16384 + qa);
            #pragma unroll
            for (int ni = 0; ni < 8; ni++) {
                uint32_t ka = SWZ((b_row + ni * 8) * 128 + ks * 32 + b_kb);
                uint32_t kf[2], klf[2];
                ldmx2(kf,  sbase + kvb + ka);
                ldmx2(klf, sbase + kvb + 16384 + ka);
                mma16816(Sacc[ni], ah, kf);
                mma16816(Sacc[ni], ah, klf);
                mma16816(Sacc[ni], al, kf);
            }
        }

        // ---- exp + attnW store + rowsum + repack to A-fragments ----
        uint32_t pah[4][4], pal[4][4];
        float* Wrow = attnW + ((size_t)bh * S_LEN + q0 + wq * 16 + (lane >> 2)) * S_LEN
                    + k0 + wk * 64 + (lane & 3) * 2;
        #pragma unroll
        for (int ni = 0; ni < 8; ni++) {
            float e0 = __expf(Sacc[ni][0] * SCALE);
            float e1 = __expf(Sacc[ni][1] * SCALE);
            float e2 = __expf(Sacc[ni][2] * SCALE);
            float e3 = __expf(Sacc[ni][3] * SCALE);
            rs0 += e0 + e1;
            rs1 += e2 + e3;
            *(float2*)(Wrow + ni * 8)                      = make_float2(e0, e1);
            *(float2*)(Wrow + (size_t)8 * S_LEN + ni * 8)  = make_float2(e2, e3);
            uint32_t h01, l01, h23, l23;
            split2(e0, e1, h01, l01);
            split2(e2, e3, h23, l23);
            int kp = ni >> 1, o = (ni & 1) * 2;
            pah[kp][o] = h01; pah[kp][o + 1] = h23;
            pal[kp][o] = l01; pal[kp][o + 1] = l23;
        }

        // ---- O += P @ V (warp: 16q x 64d over its 64-key half) ----
        #pragma unroll
        for (int kp = 0; kp < 4; kp++) {
            #pragma unroll
            for (int nd = 0; nd < 8; nd++) {
                uint32_t va = SWZ((v_row + kp * 16) * 128 + nd * 16);
                uint32_t vhf[2], vlf[2];
                ldmx2t(vhf, sbase + kvb + 32768 + va);
                ldmx2t(vlf, sbase + kvb + 49152 + va);
                mma16816(Oacc[nd], pah[kp], vhf);
                mma16816(Oacc[nd], pal[kp], vhf);
                mma16816(Oacc[nd], pah[kp], vlf);
            }
        }
        __syncthreads();
    }

    // ---- epilogue: cross-half reduction, normalize, store split ctx ----
    float* rsb = (float*)(sm + AT_RS);
    rs0 += __shfl_xor_sync(0xffffffffu, rs0, 1);
    rs0 += __shfl_xor_sync(0xffffffffu, rs0, 2);
    rs1 += __shfl_xor_sync(0xffffffffu, rs1, 1);
    rs1 += __shfl_xor_sync(0xffffffffu, rs1, 2);
    if ((lane & 3) == 0) {
        rsb[wk * 128 + wq * 16 + (lane >> 2)]     = rs0;
        rsb[wk * 128 + wq * 16 + 8 + (lane >> 2)] = rs1;
    }
    if (wk == 1) {
        float* ob = (float*)(sm + AT_OBUF);
        int r0 = wq * 16 + (lane >> 2);
        #pragma unroll
        for (int nd = 0; nd < 8; nd++) {
            *(float2*)&ob[r0 * 64 + nd * 8 + (lane & 3) * 2]       = make_float2(Oacc[nd][0], Oacc[nd][1]);
            *(float2*)&ob[(r0 + 8) * 64 + nd * 8 + (lane & 3) * 2] = make_float2(Oacc[nd][2], Oacc[nd][3]);
        }
    }
    __syncthreads();
    if (wk == 0) {
        float* ob = (float*)(sm + AT_OBUF);
        int r0 = wq * 16 + (lane >> 2);
        int r1 = r0 + 8;
        float inv0 = 1.f / (rsb[r0] + rsb[128 + r0]);
        float inv1 = 1.f / (rsb[r1] + rsb[128 + r1]);
        const int b = bh >> 4, h = bh & 15;
        size_t i0 = ((size_t)b * S_LEN + q0 + r0) * DM + h * 64 + (lane & 3) * 2;
        size_t i1 = ((size_t)b * S_LEN + q0 + r1) * DM + h * 64 + (lane & 3) * 2;
        #pragma unroll
        for (int nd = 0; nd < 8; nd++) {
            float2 p0 = *(float2*)&ob[r0 * 64 + nd * 8 + (lane & 3) * 2];
            float2 p1 = *(float2*)&ob[r1 * 64 + nd * 8 + (lane & 3) * 2];
            uint32_t hw, lw;
            split2((Oacc[nd][0] + p0.x) * inv0, (Oacc[nd][1] + p0.y) * inv0, hw, lw);
            *(uint32_t*)(g_Ch + i0 + nd * 8) = hw;
            *(uint32_t*)(g_Cl + i0 + nd * 8) = lw;
            split2((Oacc[nd][2] + p1.x) * inv1, (Oacc[nd][3] + p1.y) * inv1, hw, lw);
            *(uint32_t*)(g_Ch + i1 + nd * 8) = hw;
            *(uint32_t*)(g_Cl + i1 + nd * 8) = lw;
        }
        if ((lane & 3) == 0) {
            g_inv[bh * S_LEN + q0 + r0] = inv0;
            g_inv[bh * S_LEN + q0 + r1] = inv1;
        }
    }
}

// ---------------------------------------------------------------------------
// Normalize attn_weights in place (HBM-bound)
// ---------------------------------------------------------------------------
__global__ void norm_kernel(float* __restrict__ attnW)
{
    const size_t total  = (size_t)BH * S_LEN * (S_LEN / 4);
    const size_t stride = (size_t)gridDim.x * blockDim.x;
    for (size_t i = (size_t)blockIdx.x * blockDim.x + threadIdx.x; i < total; i += stride) {
        float inv = g_inv[i >> 9];
        float4 w = ((float4*)attnW)[i];
        w.x *= inv; w.y *= inv; w.z *= inv; w.w *= inv;
        ((float4*)attnW)[i] = w;
    }
}

// ---------------------------------------------------------------------------
// Launcher
// ---------------------------------------------------------------------------
#define GEMM_SMEM_BYTES 131072

extern "C" void kernel_launch(void* const* d_in, const int* in_sizes, int n_in,
                              void* d_out, int out_size)
{
    const float* x  = (const float*)d_in[0];
    const float* Wq = (const float*)d_in[1];
    const float* Wk = (const float*)d_in[2];
    const float* Wv = (const float*)d_in[3];
    const float* Wo = (const float*)d_in[4];

    float* out   = (float*)d_out;
    float* attnW = out + (size_t)MROWS * DM;

    cudaFuncSetAttribute(qkv_kernel,
                         cudaFuncAttributeMaxDynamicSharedMemorySize, GEMM_SMEM_BYTES);
    cudaFuncSetAttribute(proj_kernel,
                         cudaFuncAttributeMaxDynamicSharedMemorySize, GEMM_SMEM_BYTES);
    cudaFuncSetAttribute(attn_kernel,
                         cudaFuncAttributeMaxDynamicSharedMemorySize, AT_SMEM_BYTES);

    __nv_bfloat16 *Xh, *Xl, *Wqh, *Wql, *Wkh, *Wkl, *Wvh, *Wvl, *Woh, *Wol;
    cudaGetSymbolAddress((void**)&Xh,  g_Xh);  cudaGetSymbolAddress((void**)&Xl,  g_Xl);
    cudaGetSymbolAddress((void**)&Wqh, g_Wqh); cudaGetSymbolAddress((void**)&Wql, g_Wql);
    cudaGetSymbolAddress((void**)&Wkh, g_Wkh); cudaGetSymbolAddress((void**)&Wkl, g_Wkl);
    cudaGetSymbolAddress((void**)&Wvh, g_Wvh); cudaGetSymbolAddress((void**)&Wvl, g_Wvl);
    cudaGetSymbolAddress((void**)&Woh, g_Woh); cudaGetSymbolAddress((void**)&Wol, g_Wol);

    split_kernel<<<2048, 256>>>(x,  Xh,  Xl,  MROWS * DM / 2);
    split_kernel<<<1024, 256>>>(Wq, Wqh, Wql, DM * DM / 2);
    split_kernel<<<1024, 256>>>(Wk, Wkh, Wkl, DM * DM / 2);
    split_kernel<<<1024, 256>>>(Wv, Wvh, Wvl, DM * DM / 2);
    split_kernel<<<1024, 256>>>(Wo, Woh, Wol, DM * DM / 2);

    dim3 gq(DM / 128, MROWS / 128, 3);
    qkv_kernel<<<gq, 256, GEMM_SMEM_BYTES>>>();

    dim3 ga(S_LEN / 128, BH);
    attn_kernel<<<ga, 512, AT_SMEM_BYTES>>>(attnW);

    norm_kernel<<<1184, 256>>>(attnW);

    dim3 gp(DM / 128, MROWS / 128);
    proj_kernel<<<gp, 256, GEMM_SMEM_BYTES>>>(out);
}